// round 1
// baseline (speedup 1.0000x reference)
#include <cuda_runtime.h>
#include <math.h>

#define NB 8
#define NC 128
#define NH 128
#define NW 128
#define NL (NH*NW)          // 16384
#define NMID 32
#define KTOT 416            // 128 x + 128 nsum + 128 diff + 32 silu
#define NROWBLK (NB*NH)     // 1024
#define NTOT (NB*NC*NL)     // 16777216

// ---------------- device scratch (static, no runtime allocation) ----------------
__device__ float g_y2[NTOT];                 // 64MB intermediate before BN
__device__ float g_gap[NB][NC];
__device__ float g_M1[NC*NC];
__device__ float g_M2[NC*NC];
__device__ __align__(16) float g_Bt[KTOT*NC];   // folded weights, [k][oc]
__device__ float g_ck[NB][3][NC];
__device__ float g_u[NB][NMID];
__device__ float g_b2p[NC];
__device__ float g_psum[NC*NROWBLK];
__device__ float g_psq[NC*NROWBLK];
__device__ float g_scale[NC];
__device__ float g_shift[NC];

// ---------------- gap: per (b,c) spatial mean ----------------
__global__ void k_gap(const float* __restrict__ x) {
    int bc = blockIdx.x;
    int tid = threadIdx.x;
    __shared__ float red[256];
    const float4* p = (const float4*)(x + (size_t)bc * NL);
    float s = 0.f;
    for (int t = tid; t < NL/4; t += 256) { float4 v = p[t]; s += (v.x + v.y) + (v.z + v.w); }
    red[tid] = s; __syncthreads();
    for (int k = 128; k > 0; k >>= 1) { if (tid < k) red[tid] += red[tid+k]; __syncthreads(); }
    if (tid == 0) g_gap[bc >> 7][bc & 127] = red[0] * (1.0f / NL);
}

// ---------------- M1 = Wout diag(w1) Win ; M2 = 0.25 Wout diag(w0+w2) Win ----------------
__global__ void k_prep1(const float* __restrict__ win, const float* __restrict__ wdw,
                        const float* __restrict__ wout) {
    int o = blockIdx.x, c = threadIdx.x;
    float a1 = 0.f, a2 = 0.f;
    for (int s = 0; s < NC; s++) {
        float wo  = wout[o*NC + s];
        float w1  = wdw[s*3 + 1];
        float w02 = wdw[s*3 + 0] + wdw[s*3 + 2];
        float wi  = win[s*NC + c];
        a1 = fmaf(wo * w1,  wi, a1);
        a2 = fmaf(wo * w02, wi, a2);
    }
    g_M1[o*NC + c] = a1;
    g_M2[o*NC + c] = 0.25f * a2;
}

// ---------------- Bt = [Wp(M1+I) | Wp M2 | dw*Wp | Wp W2], b2p = Wp b2 ----------------
__global__ void k_prep2(const float* __restrict__ wp, const float* __restrict__ w2,
                        const float* __restrict__ b2, const float* __restrict__ dwp) {
    int o = blockIdx.x, c = threadIdx.x;
    __shared__ float wps[NC];
    __shared__ float red[NC];
    wps[c] = wp[o*NC + c];
    __syncthreads();
    float a1 = 0.f, a2 = 0.f;
    for (int t = 0; t < NC; t++) {
        float w  = wps[t];
        float m1 = g_M1[t*NC + c];
        if (t == c) m1 += 1.0f;           // +I carries the raw-x term of y_diff
        a1 = fmaf(w, m1, a1);
        a2 = fmaf(w, g_M2[t*NC + c], a2);
    }
    g_Bt[c*NC + o]          = a1;
    g_Bt[(NC + c)*NC + o]   = a2;
    g_Bt[(2*NC + c)*NC + o] = dwp[0] * wps[c];
    if (c < NMID) {
        float s = 0.f;
        for (int t = 0; t < NC; t++) s = fmaf(wps[t], w2[t*NMID + c], s);
        g_Bt[(3*NC + c)*NC + o] = s;
    }
    red[c] = wps[c] * b2[c];
    __syncthreads();
    for (int s = 64; s > 0; s >>= 1) { if (c < s) red[c] += red[c+s]; __syncthreads(); }
    if (c == 0) g_b2p[o] = red[0];
}

// ---------------- per-batch vectors: gap_n, c_k, u ----------------
__global__ void k_prep3(const float* __restrict__ wci, const float* __restrict__ wdwch,
                        const float* __restrict__ wco, const float* __restrict__ w1) {
    int b = blockIdx.x, c = threadIdx.x;
    __shared__ float red[NC];
    __shared__ float gs[NC];
    __shared__ float g2s[NC];
    float g = g_gap[b][c];
    red[c] = g * g; __syncthreads();
    for (int s = 64; s > 0; s >>= 1) { if (c < s) red[c] += red[c+s]; __syncthreads(); }
    float nrm = fmaxf(sqrtf(red[0]), 1e-12f);
    gs[c] = g / nrm;
    __syncthreads();
    float a = 0.f;
    for (int j = 0; j < NC; j++) a = fmaf(gs[j], wco[j*NC + c], a);   // g2 = Wco^T gap_n
    g2s[c] = a;
    __syncthreads();
    for (int k = 0; k < 3; k++) {
        float s = 0.f;
        for (int t = 0; t < NC; t++) s = fmaf(wci[t*NC + c], g2s[t] * wdwch[t*3 + k], s);
        g_ck[b][k][c] = s;                // c_k = Wci^T (g2 .* wdwch[:,k])
    }
    if (c < NMID) {
        float s = 0.f;
        for (int t = 0; t < NC; t++) s = fmaf(w1[c*NC + t], gs[t], s);
        g_u[b][c] = s;                    // u = W1 gap_n
    }
}

// ---------------- main fused kernel: one image row per block ----------------
__global__ __launch_bounds__(256) void k_main(const float* __restrict__ x,
                                              const float* __restrict__ b1) {
    extern __shared__ float sm[];
    float* Fs  = sm;                      // [KTOT][128] feature tile
    float* vs  = sm + KTOT*NW;            // [128]
    float* cks = vs + NW;                 // [3][128]
    float* us  = cks + 3*NC;              // [32]
    float* b1s = us + NMID;               // [32]

    const int tid = threadIdx.x;
    const int b = blockIdx.x >> 7;
    const int i = blockIdx.x & 127;
    const float* xb = x + (size_t)b * NC * NL;

    for (int t = tid; t < 3*NC; t += 256) cks[t] = (&g_ck[b][0][0])[t];
    if (tid < NMID) { us[tid] = g_u[b][tid]; b1s[tid] = b1[tid]; }

    // ---- build F: x (rows 0..127), nsum (128..255), diffsum (256..383) ----
    for (int it = tid; it < NC*NW; it += 256) {
        int c = it >> 7, j = it & 127;
        const float* xr = xb + c*NL + i*NW;
        float xc = xr[j];
        // flat-sequence neighbors (zero only at global sequence ends)
        float l = (j > 0)    ? xr[j-1] : ((i > 0)    ? xb[c*NL + (i-1)*NW + (NW-1)] : 0.0f);
        float r = (j < NW-1) ? xr[j+1] : ((i < NH-1) ? xb[c*NL + (i+1)*NW]          : 0.0f);
        float u = (i > 0)    ? xb[c*NL + (i-1)*NW + j]
                             : ((j > 0)    ? xb[c*NL + (NH-1)*NW + (j-1)] : 0.0f);
        float d = (i < NH-1) ? xb[c*NL + (i+1)*NW + j]
                             : ((j < NW-1) ? xb[c*NL + (j+1)]             : 0.0f);
        // reflect-pad neighbors for diff branch
        float lr = (j > 0)    ? xr[j-1] : xr[1];
        float rr = (j < NW-1) ? xr[j+1] : xr[NW-2];
        float ur = (i > 0)    ? xb[c*NL + (i-1)*NW + j] : xb[c*NL + NW + j];
        float dr = (i < NH-1) ? xb[c*NL + (i+1)*NW + j] : xb[c*NL + (NH-2)*NW + j];
        Fs[c*NW + j]          = xc;
        Fs[(NC + c)*NW + j]   = (l + r) + (u + d);
        Fs[(2*NC + c)*NW + j] = 0.25f * ((fabsf(xc-lr) + fabsf(xc-rr)) + (fabsf(xc-ur) + fabsf(xc-dr)));
    }
    __syncthreads();

    // ---- v[j] = sum_c c0*x[p-1] + c1*x[p] + c2*x[p+1] (flat order) ----
    if (tid < NW) {
        int j = tid;
        float v = 0.0f;
        for (int c = 0; c < NC; c++) {
            float xm = (j > 0)    ? Fs[c*NW + j-1]
                                  : ((i > 0)    ? xb[c*NL + (i-1)*NW + (NW-1)] : 0.0f);
            float xp = (j < NW-1) ? Fs[c*NW + j+1]
                                  : ((i < NH-1) ? xb[c*NL + (i+1)*NW] : 0.0f);
            v = fmaf(cks[c], xm, v);
            v = fmaf(cks[NC + c], Fs[c*NW + j], v);
            v = fmaf(cks[2*NC + c], xp, v);
        }
        vs[j] = v;
    }
    __syncthreads();

    // ---- silu rows: F[384+m][j] = silu(u_m * v_j + b1_m) ----
    for (int it = tid; it < NMID*NW; it += 256) {
        int m = it >> 7, j = it & 127;
        float z = fmaf(us[m], vs[j], b1s[m]);
        float sg = 1.0f / (1.0f + expf(-z));
        Fs[(3*NC + m)*NW + j] = z * sg;
    }
    __syncthreads();

    // ---- GEMM: y2[o][j] = sum_k Bt[k][o] * F[k][j]  (8x8 register tile/thread) ----
    const int tx = tid & 15, ty = tid >> 4;
    const int j0 = tx*8, o0 = ty*8;
    float acc[8][8];
    #pragma unroll
    for (int r = 0; r < 8; r++)
        #pragma unroll
        for (int q = 0; q < 8; q++) acc[r][q] = 0.0f;

    const float* Bp = g_Bt + o0;
    const float* Fp = Fs + j0;
    #pragma unroll 4
    for (int k = 0; k < KTOT; k++) {
        float4 ba = *(const float4*)(Bp + k*NC);
        float4 bbv = *(const float4*)(Bp + k*NC + 4);
        float4 fa = *(const float4*)(Fp + k*NW);
        float4 fbv = *(const float4*)(Fp + k*NW + 4);
        float bv[8] = {ba.x, ba.y, ba.z, ba.w, bbv.x, bbv.y, bbv.z, bbv.w};
        float fv[8] = {fa.x, fa.y, fa.z, fa.w, fbv.x, fbv.y, fbv.z, fbv.w};
        #pragma unroll
        for (int r = 0; r < 8; r++)
            #pragma unroll
            for (int q = 0; q < 8; q++)
                acc[r][q] = fmaf(bv[r], fv[q], acc[r][q]);
    }

    // ---- epilogue: write y2 + deterministic BN partials ----
    float psumr[8], psqr[8];
    #pragma unroll
    for (int r = 0; r < 8; r++) {
        float bb = g_b2p[o0 + r];
        float s = 0.f, sq = 0.f;
        float vals[8];
        #pragma unroll
        for (int q = 0; q < 8; q++) {
            float v = acc[r][q] + bb;
            vals[q] = v; s += v; sq = fmaf(v, v, sq);
        }
        float4* dst = (float4*)&g_y2[(size_t)((b*NC + o0 + r))*NL + i*NW + j0];
        dst[0] = make_float4(vals[0], vals[1], vals[2], vals[3]);
        dst[1] = make_float4(vals[4], vals[5], vals[6], vals[7]);
        psumr[r] = s; psqr[r] = sq;
    }
    __syncthreads();                       // done reading Fs -> reuse for reduction
    float* sred = Fs;                      // [128][16] sum, then [128][16] sumsq
    #pragma unroll
    for (int r = 0; r < 8; r++) {
        sred[(o0 + r)*16 + tx]        = psumr[r];
        sred[2048 + (o0 + r)*16 + tx] = psqr[r];
    }
    __syncthreads();
    if (tid < NC) {
        float s = 0.f, sq = 0.f;
        #pragma unroll
        for (int t = 0; t < 16; t++) { s += sred[tid*16 + t]; sq += sred[2048 + tid*16 + t]; }
        g_psum[tid*NROWBLK + blockIdx.x] = s;
        g_psq [tid*NROWBLK + blockIdx.x] = sq;
    }
}

// ---------------- BN stats over 1024 block-partials per channel ----------------
__global__ void k_bnstat(const float* __restrict__ gamma, const float* __restrict__ beta) {
    int c = blockIdx.x, tid = threadIdx.x;
    __shared__ float s1[256], s2[256];
    float a = 0.f, q = 0.f;
    for (int t = tid; t < NROWBLK; t += 256) { a += g_psum[c*NROWBLK + t]; q += g_psq[c*NROWBLK + t]; }
    s1[tid] = a; s2[tid] = q; __syncthreads();
    for (int s = 128; s > 0; s >>= 1) {
        if (tid < s) { s1[tid] += s1[tid+s]; s2[tid] += s2[tid+s]; }
        __syncthreads();
    }
    if (tid == 0) {
        const float invN = 1.0f / (float)(NB * NL);
        float mu  = s1[0] * invN;
        float var = s2[0] * invN - mu * mu;
        float rs  = rsqrtf(var + 1e-5f);
        float sc  = gamma[c] * rs;
        g_scale[c] = sc;
        g_shift[c] = beta[c] - mu * sc;
    }
}

// ---------------- normalize ----------------
__global__ void k_norm(float* __restrict__ out) {
    int idx = blockIdx.x * blockDim.x + threadIdx.x;     // float4 index
    float4 v = ((const float4*)g_y2)[idx];
    int c = (idx >> 12) & 127;                            // 4096 float4 per channel-plane
    float sc = g_scale[c], sh = g_shift[c];
    v.x = fmaf(v.x, sc, sh); v.y = fmaf(v.y, sc, sh);
    v.z = fmaf(v.z, sc, sh); v.w = fmaf(v.w, sc, sh);
    ((float4*)out)[idx] = v;
}

// ---------------- launcher ----------------
extern "C" void kernel_launch(void* const* d_in, const int* in_sizes, int n_in,
                              void* d_out, int out_size) {
    const float* x            = (const float*)d_in[0];
    const float* w_spatial_in = (const float*)d_in[1];
    const float* w_dw_spatial = (const float*)d_in[2];
    const float* w_spatial_out= (const float*)d_in[3];
    const float* w_ch_in      = (const float*)d_in[4];
    const float* w_ch_dw      = (const float*)d_in[5];
    const float* w_ch_out     = (const float*)d_in[6];
    const float* w_mlp1       = (const float*)d_in[7];
    const float* b_mlp1       = (const float*)d_in[8];
    const float* w_mlp2       = (const float*)d_in[9];
    const float* b_mlp2       = (const float*)d_in[10];
    const float* diff_weight  = (const float*)d_in[11];
    const float* bn_gamma     = (const float*)d_in[12];
    const float* bn_beta      = (const float*)d_in[13];
    const float* w_out_proj   = (const float*)d_in[14];
    float* out = (float*)d_out;

    const int SMEM = (KTOT*NW + NW + 3*NC + 2*NMID) * (int)sizeof(float);  // 215296 B
    cudaFuncSetAttribute(k_main, cudaFuncAttributeMaxDynamicSharedMemorySize, SMEM);

    k_gap  <<<NB*NC, 256>>>(x);
    k_prep1<<<NC, NC>>>(w_spatial_in, w_dw_spatial, w_spatial_out);
    k_prep2<<<NC, NC>>>(w_out_proj, w_mlp2, b_mlp2, diff_weight);
    k_prep3<<<NB, NC>>>(w_ch_in, w_ch_dw, w_ch_out, w_mlp1);
    k_main <<<NROWBLK, 256, SMEM>>>(x, b_mlp1);
    k_bnstat<<<NC, 256>>>(bn_gamma, bn_beta);
    k_norm <<<NTOT/4/256, 256>>>(out);
}

// round 3
// speedup vs baseline: 1.4351x; 1.4351x over previous
#include <cuda_runtime.h>
#include <math.h>
#include <stdint.h>

#define NB 8
#define NC 128
#define NH 128
#define NW 128
#define NL (NH*NW)          // 16384
#define NMID 32
#define KTOT 416            // 128 x + 128 nsum + 128 diff + 32 silu
#define NSTAGE 52           // KTOT/8
#define NROWBLK (NB*NH)     // 1024
#define NTOT (NB*NC*NL)     // 16777216

// ---------------- device scratch ----------------
__device__ float g_y2[NTOT];
__device__ float g_gap[NB][NC];
__device__ __align__(16) float g_Bt[KTOT*NC];   // folded weights [k][o], tf32-rounded
__device__ float g_ck[NB][3][NC];
__device__ float g_u[NB][NMID];
__device__ float g_b2p[NC];
__device__ float g_psum[NC*NROWBLK];
__device__ float g_psq[NC*NROWBLK];
__device__ float g_scale[NC];
__device__ float g_shift[NC];

__device__ __forceinline__ float to_tf32(float x) {
    uint32_t o;
    asm("cvt.rna.tf32.f32 %0, %1;" : "=r"(o) : "f"(x));
    return __uint_as_float(o);
}
__device__ __forceinline__ void mma_tf32(float* d, const uint32_t* a, const uint32_t* b) {
    asm volatile("mma.sync.aligned.m16n8k8.row.col.f32.tf32.tf32.f32 "
        "{%0,%1,%2,%3}, {%4,%5,%6,%7}, {%8,%9}, {%0,%1,%2,%3};"
        : "+f"(d[0]), "+f"(d[1]), "+f"(d[2]), "+f"(d[3])
        : "r"(a[0]), "r"(a[1]), "r"(a[2]), "r"(a[3]), "r"(b[0]), "r"(b[1]));
}

// ---------------- gap: per (b,c) spatial mean ----------------
__global__ void k_gap(const float* __restrict__ x) {
    int bc = blockIdx.x;
    int tid = threadIdx.x;
    __shared__ float red[256];
    const float4* p = (const float4*)(x + (size_t)bc * NL);
    float s = 0.f;
    for (int t = tid; t < NL/4; t += 256) { float4 v = p[t]; s += (v.x + v.y) + (v.z + v.w); }
    red[tid] = s; __syncthreads();
    for (int k = 128; k > 0; k >>= 1) { if (tid < k) red[tid] += red[tid+k]; __syncthreads(); }
    if (tid == 0) g_gap[bc >> 7][bc & 127] = red[0] * (1.0f / NL);
}

// ---------------- fold all weights into g_Bt (tf32-rounded) ----------------
__global__ void k_prepw(const float* __restrict__ wp,  const float* __restrict__ wout,
                        const float* __restrict__ wdw, const float* __restrict__ win,
                        const float* __restrict__ w2,  const float* __restrict__ b2,
                        const float* __restrict__ dwp) {
    int o = blockIdx.x, c = threadIdx.x;
    __shared__ float wps[NC], q[NC], red[NC];
    wps[c] = wp[o*NC + c];
    __syncthreads();
    float a = 0.f;
    for (int t = 0; t < NC; t++) a = fmaf(wps[t], wout[t*NC + c], a);   // (Wp*Wout)[o,c]
    q[c] = a;
    __syncthreads();
    float a1 = 0.f, a2 = 0.f;
    for (int s = 0; s < NC; s++) {
        float qs = q[s];
        float w1 = wdw[s*3 + 1], w02 = wdw[s*3 + 0] + wdw[s*3 + 2];
        float wi = win[s*NC + c];
        a1 = fmaf(qs * w1,  wi, a1);
        a2 = fmaf(qs * w02, wi, a2);
    }
    a1 += wps[c];                               // +Wp (raw-x path of y_diff)
    g_Bt[c*NC + o]          = to_tf32(a1);              // phase0: B1 = Wp(M1+I)
    g_Bt[(NC + c)*NC + o]   = to_tf32(0.25f * a2);      // phase1: B2
    g_Bt[(2*NC + c)*NC + o] = to_tf32(dwp[0] * wps[c]); // phase2: B3 = dw*Wp
    if (c < NMID) {
        float s4 = 0.f;
        for (int t = 0; t < NC; t++) s4 = fmaf(wps[t], w2[t*NMID + c], s4);
        g_Bt[(3*NC + c)*NC + o] = to_tf32(s4);          // phase3: Wp*W2
    }
    red[c] = wps[c] * b2[c];
    __syncthreads();
    for (int s = 64; s > 0; s >>= 1) { if (c < s) red[c] += red[c+s]; __syncthreads(); }
    if (c == 0) g_b2p[o] = red[0];
}

// ---------------- per-batch vectors: gap_n, c_k, u ----------------
__global__ void k_prep3(const float* __restrict__ wci, const float* __restrict__ wdwch,
                        const float* __restrict__ wco, const float* __restrict__ w1) {
    int b = blockIdx.x, c = threadIdx.x;
    __shared__ float red[NC], gs[NC], g2s[NC];
    float g = g_gap[b][c];
    red[c] = g * g; __syncthreads();
    for (int s = 64; s > 0; s >>= 1) { if (c < s) red[c] += red[c+s]; __syncthreads(); }
    float nrm = fmaxf(sqrtf(red[0]), 1e-12f);
    gs[c] = g / nrm;
    __syncthreads();
    float a = 0.f;
    for (int j = 0; j < NC; j++) a = fmaf(gs[j], wco[j*NC + c], a);
    g2s[c] = a;
    __syncthreads();
    float s0 = 0.f, s1 = 0.f, s2 = 0.f;
    for (int t = 0; t < NC; t++) {
        float wv = wci[t*NC + c] * g2s[t];
        s0 = fmaf(wv, wdwch[t*3 + 0], s0);
        s1 = fmaf(wv, wdwch[t*3 + 1], s1);
        s2 = fmaf(wv, wdwch[t*3 + 2], s2);
    }
    g_ck[b][0][c] = s0; g_ck[b][1][c] = s1; g_ck[b][2][c] = s2;
    if (c < NMID) {
        float s = 0.f;
        for (int t = 0; t < NC; t++) s = fmaf(w1[c*NC + t], gs[t], s);
        g_u[b][c] = s;
    }
}

// ---------------- main fused kernel ----------------
// dyn smem layout (bytes):
//   [0,4096)        small: vs[128] sv[256] cks[384] us[32] b1s[32] b2s[128]
//   [4096,12288)    As: weight staging, 2 x (8x128) floats (swizzled)
//   [12288,225280)  Fs: feature tile 416x128 floats (swizzled)
#define OFF_AS 4096
#define OFF_FS 12288
#define SMEM_MAIN (OFF_FS + KTOT*NC*4)

// element swizzle: idx(k, j) = k*128 + (j ^ ((k&3)<<3))
__global__ __launch_bounds__(256)
void k_main(const float* __restrict__ x, const float* __restrict__ b1) {
    extern __shared__ char sm[];
    float* vs  = (float*)(sm);            // [128]
    float* sv  = (float*)(sm + 512);      // [2][128]
    float* cks = (float*)(sm + 1536);     // [3][128]
    float* us  = (float*)(sm + 3072);     // [32]
    float* b1s = (float*)(sm + 3200);     // [32]
    float* b2s = (float*)(sm + 3328);     // [128]
    float* Asm = (float*)(sm + OFF_AS);   // [2][8*128]
    float* Fs  = (float*)(sm + OFF_FS);   // [416*128]

    const int tid = threadIdx.x;
    const int b = blockIdx.x >> 7;
    const int i = blockIdx.x & 127;
    const float* xb = x + (size_t)b * (NC*NL);

    // prefetch weight stage 0 early
    float4 pre = *(const float4*)(g_Bt + tid*4);

    for (int t = tid; t < 3*NC; t += 256) cks[t] = (&g_ck[b][0][0])[t];
    if (tid < NMID) { us[tid] = g_u[b][tid]; b1s[tid] = b1[tid]; }
    if (tid < NC)   b2s[tid] = g_b2p[tid];

    // ---- build x phase: Fs rows 0..127 (float4-safe swizzle) ----
    for (int it = tid; it < 4096; it += 256) {
        int c = it >> 5, jf4 = it & 31;
        float4 v = *(const float4*)(xb + c*NL + i*NW + (jf4 << 2));
        v.x = to_tf32(v.x); v.y = to_tf32(v.y); v.z = to_tf32(v.z); v.w = to_tf32(v.w);
        ((float4*)Fs)[c*32 + (jf4 ^ ((c&3)<<1))] = v;
    }
    __syncthreads();

    // ---- v partials from x rows in smem ----
    {
        int j = tid & 127, half = tid >> 7, c0 = half << 6;
        float v = 0.f;
        for (int c = c0; c < c0 + 64; c++) {
            int sw = (c&3) << 3;
            float xc = Fs[c*NC + (j ^ sw)];
            float xm = (j > 0)   ? Fs[c*NC + ((j-1) ^ sw)]
                                 : ((i > 0)   ? xb[c*NL + (i-1)*NW + 127] : 0.f);
            float xp = (j < 127) ? Fs[c*NC + ((j+1) ^ sw)]
                                 : ((i < 127) ? xb[c*NL + (i+1)*NW] : 0.f);
            v = fmaf(cks[c], xm, v);
            v = fmaf(cks[NC + c], xc, v);
            v = fmaf(cks[2*NC + c], xp, v);
        }
        sv[tid] = v;
    }

    // ---- build nsum (rows 128..255) and diff (rows 256..383) ----
    for (int it = tid; it < NC*NW; it += 256) {
        int c = it >> 7, j = it & 127;
        const float* xr = xb + c*NL + i*NW;
        float xc = xr[j];
        float xl = (j > 0)   ? xr[j-1] : 0.f;
        float xrr= (j < 127) ? xr[j+1] : 0.f;
        float xu = (i > 0)   ? xb[c*NL + (i-1)*NW + j] : 0.f;
        float xd = (i < 127) ? xb[c*NL + (i+1)*NW + j] : 0.f;
        // flat-order neighbors (wrap across rows; zero at sequence ends)
        float l = (j > 0)   ? xl  : ((i > 0)   ? xb[c*NL + (i-1)*NW + 127] : 0.f);
        float r = (j < 127) ? xrr : ((i < 127) ? xb[c*NL + (i+1)*NW]       : 0.f);
        float u = (i > 0)   ? xu  : ((j > 0)   ? xb[c*NL + 127*NW + (j-1)] : 0.f);
        float d = (i < 127) ? xd  : ((j < 127) ? xb[c*NL + (j+1)]          : 0.f);
        // reflect-pad neighbors
        float lr = (j > 0)   ? xl  : xr[1];
        float rr = (j < 127) ? xrr : xr[126];
        float ur = (i > 0)   ? xu  : xb[c*NL + NW + j];
        float dr = (i < 127) ? xd  : xb[c*NL + 126*NW + j];
        int sw = (c&3) << 3;   // rows 128+c and 256+c have same (k&3) as c
        Fs[(NC + c)*NC + (j ^ sw)] = to_tf32((l + r) + (u + d));
        Fs[(2*NC + c)*NC + (j ^ sw)] =
            to_tf32(0.25f * ((fabsf(xc-lr) + fabsf(xc-rr)) + (fabsf(xc-ur) + fabsf(xc-dr))));
    }
    __syncthreads();
    if (tid < 128) vs[tid] = sv[tid] + sv[128 + tid];
    __syncthreads();

    // ---- silu rows 384..415 ----
    for (int it = tid; it < NMID*NW; it += 256) {
        int m = it >> 7, j = it & 127;
        float z = fmaf(us[m], vs[j], b1s[m]);
        Fs[(3*NC + m)*NC + (j ^ ((m&3)<<3))] = to_tf32(z / (1.f + expf(-z)));
    }

    // store weight stage 0 (swizzled), kick off GEMM
    {
        int krow = tid >> 5, c4 = tid & 31;
        ((float4*)Asm)[krow*32 + (c4 ^ ((krow&3)<<1))] = pre;
    }
    __syncthreads();

    // ---- GEMM: D[o][j] = sum_k Bt[k][o] * F[k][j], tf32 mma.sync ----
    const int lane = tid & 31, g = lane >> 2, tg = lane & 3;
    const int w = tid >> 5, mbase = (w >> 2) * 64, nbase = (w & 3) * 32;
    const uint32_t* Fu = (const uint32_t*)Fs;
    float dacc[4][4][4];
    #pragma unroll
    for (int mt = 0; mt < 4; mt++)
        #pragma unroll
        for (int nt = 0; nt < 4; nt++)
            #pragma unroll
            for (int q = 0; q < 4; q++) dacc[mt][nt][q] = 0.f;

    for (int kb = 0; kb < NSTAGE; kb++) {
        const uint32_t* As = (const uint32_t*)(Asm + (kb & 1) * 1024);
        if (kb < NSTAGE-1)
            pre = *(const float4*)(g_Bt + (kb+1)*1024 + tid*4);

        uint32_t af[4][4], bf[4][2];
        const int swa = tg << 3;
        #pragma unroll
        for (int nt = 0; nt < 4; nt++) {
            int n = nbase + nt*8 + g;
            int k0 = kb*8 + tg;
            bf[nt][0] = Fu[k0*NC + (n ^ swa)];
            bf[nt][1] = Fu[(k0+4)*NC + (n ^ swa)];
        }
        #pragma unroll
        for (int mt = 0; mt < 4; mt++) {
            int o = mbase + mt*16 + g;
            af[mt][0] = As[tg*NC + (o ^ swa)];
            af[mt][1] = As[tg*NC + ((o+8) ^ swa)];
            af[mt][2] = As[(tg+4)*NC + (o ^ swa)];
            af[mt][3] = As[(tg+4)*NC + ((o+8) ^ swa)];
        }
        #pragma unroll
        for (int mt = 0; mt < 4; mt++)
            #pragma unroll
            for (int nt = 0; nt < 4; nt++)
                mma_tf32(dacc[mt][nt], af[mt], bf[nt]);

        if (kb < NSTAGE-1) {
            int krow = tid >> 5, c4 = tid & 31;
            ((float4*)(Asm + ((kb+1) & 1) * 1024))[krow*32 + (c4 ^ ((krow&3)<<1))] = pre;
        }
        __syncthreads();
    }

    // ---- epilogue: bias, y2 store, BN partials ----
    float* sred = Asm;     // reuse staging area: [128][4] sums + [128][4] sumsq
    #pragma unroll
    for (int mt = 0; mt < 4; mt++) {
        int o0 = mbase + mt*16 + g, o1 = o0 + 8;
        float bb0 = b2s[o0], bb1 = b2s[o1];
        float* row0 = &g_y2[(size_t)(b*NC + o0) * NL + i*NW];
        float* row1 = &g_y2[(size_t)(b*NC + o1) * NL + i*NW];
        float s0 = 0.f, q0 = 0.f, s1 = 0.f, q1 = 0.f;
        #pragma unroll
        for (int nt = 0; nt < 4; nt++) {
            float v0 = dacc[mt][nt][0] + bb0, v1 = dacc[mt][nt][1] + bb0;
            float v2 = dacc[mt][nt][2] + bb1, v3 = dacc[mt][nt][3] + bb1;
            int j = nbase + nt*8 + 2*tg;
            *(float2*)(row0 + j) = make_float2(v0, v1);
            *(float2*)(row1 + j) = make_float2(v2, v3);
            s0 += v0 + v1; q0 = fmaf(v0, v0, q0); q0 = fmaf(v1, v1, q0);
            s1 += v2 + v3; q1 = fmaf(v2, v2, q1); q1 = fmaf(v3, v3, q1);
        }
        // reduce over tg lanes (lane bits 0,1)
        s0 += __shfl_xor_sync(0xffffffff, s0, 1); s0 += __shfl_xor_sync(0xffffffff, s0, 2);
        q0 += __shfl_xor_sync(0xffffffff, q0, 1); q0 += __shfl_xor_sync(0xffffffff, q0, 2);
        s1 += __shfl_xor_sync(0xffffffff, s1, 1); s1 += __shfl_xor_sync(0xffffffff, s1, 2);
        q1 += __shfl_xor_sync(0xffffffff, q1, 1); q1 += __shfl_xor_sync(0xffffffff, q1, 2);
        if (tg == 0) {
            int nwq = w & 3;
            sred[o0*4 + nwq] = s0; sred[512 + o0*4 + nwq] = q0;
            sred[o1*4 + nwq] = s1; sred[512 + o1*4 + nwq] = q1;
        }
    }
    __syncthreads();
    if (tid < NC) {
        float s = 0.f, q = 0.f;
        #pragma unroll
        for (int t = 0; t < 4; t++) { s += sred[tid*4 + t]; q += sred[512 + tid*4 + t]; }
        g_psum[tid*NROWBLK + blockIdx.x] = s;
        g_psq [tid*NROWBLK + blockIdx.x] = q;
    }
}

// ---------------- BN stats ----------------
__global__ void k_bnstat(const float* __restrict__ gamma, const float* __restrict__ beta) {
    int c = blockIdx.x, tid = threadIdx.x;
    __shared__ float s1[256], s2[256];
    float a = 0.f, q = 0.f;
    for (int t = tid; t < NROWBLK; t += 256) { a += g_psum[c*NROWBLK + t]; q += g_psq[c*NROWBLK + t]; }
    s1[tid] = a; s2[tid] = q; __syncthreads();
    for (int s = 128; s > 0; s >>= 1) {
        if (tid < s) { s1[tid] += s1[tid+s]; s2[tid] += s2[tid+s]; }
        __syncthreads();
    }
    if (tid == 0) {
        const float invN = 1.0f / (float)(NB * NL);
        float mu  = s1[0] * invN;
        float var = s2[0] * invN - mu * mu;
        float rs  = rsqrtf(var + 1e-5f);
        float sc  = gamma[c] * rs;
        g_scale[c] = sc;
        g_shift[c] = beta[c] - mu * sc;
    }
}

// ---------------- normalize ----------------
__global__ void k_norm(float* __restrict__ out) {
    int idx = blockIdx.x * blockDim.x + threadIdx.x;
    float4 v = ((const float4*)g_y2)[idx];
    int c = (idx >> 12) & 127;
    float sc = g_scale[c], sh = g_shift[c];
    v.x = fmaf(v.x, sc, sh); v.y = fmaf(v.y, sc, sh);
    v.z = fmaf(v.z, sc, sh); v.w = fmaf(v.w, sc, sh);
    ((float4*)out)[idx] = v;
}

// ---------------- launcher ----------------
extern "C" void kernel_launch(void* const* d_in, const int* in_sizes, int n_in,
                              void* d_out, int out_size) {
    const float* x            = (const float*)d_in[0];
    const float* w_spatial_in = (const float*)d_in[1];
    const float* w_dw_spatial = (const float*)d_in[2];
    const float* w_spatial_out= (const float*)d_in[3];
    const float* w_ch_in      = (const float*)d_in[4];
    const float* w_ch_dw      = (const float*)d_in[5];
    const float* w_ch_out     = (const float*)d_in[6];
    const float* w_mlp1       = (const float*)d_in[7];
    const float* b_mlp1       = (const float*)d_in[8];
    const float* w_mlp2       = (const float*)d_in[9];
    const float* b_mlp2       = (const float*)d_in[10];
    const float* diff_weight  = (const float*)d_in[11];
    const float* bn_gamma     = (const float*)d_in[12];
    const float* bn_beta      = (const float*)d_in[13];
    const float* w_out_proj   = (const float*)d_in[14];
    float* out = (float*)d_out;

    cudaFuncSetAttribute(k_main, cudaFuncAttributeMaxDynamicSharedMemorySize, SMEM_MAIN);

    k_prepw<<<NC, NC>>>(w_out_proj, w_spatial_out, w_dw_spatial, w_spatial_in,
                        w_mlp2, b_mlp2, diff_weight);
    k_gap  <<<NB*NC, 256>>>(x);
    k_prep3<<<NB, NC>>>(w_ch_in, w_ch_dw, w_ch_out, w_mlp1);
    k_main <<<NROWBLK, 256, SMEM_MAIN>>>(x, b_mlp1);
    k_bnstat<<<NC, 256>>>(bn_gamma, bn_beta);
    k_norm <<<NTOT/4/256, 256>>>(out);
}

// round 4
// speedup vs baseline: 2.7576x; 1.9216x over previous
#include <cuda_runtime.h>
#include <math.h>
#include <stdint.h>

#define NB 8
#define NC 128
#define NH 128
#define NW 128
#define NL (NH*NW)          // 16384
#define NMID 32
#define KTOT 416            // 128 x + 128 nsum + 128 diff + 32 silu
#define NPAN 13             // 416/32 K-panels
#define NFROWS 288          // nsum(128) + diff(128) + silu(32)
#define NROWBLK 1024
#define NTOT (NB*NC*NL)     // 16777216

// ---------------- device scratch ----------------
__device__ float g_y2[NTOT];
__device__ __align__(16) float g_Fg[(size_t)NB*NFROWS*NL];   // 151MB feature rows
__device__ float g_gap[NB][NC];
__device__ __align__(16) float g_Bt[KTOT*NC];   // folded weights [k][o], tf32-rounded
__device__ float g_ck[NB][3][NC];
__device__ float g_u[NB][NMID];
__device__ float g_b2p[NC];
__device__ float g_psum[NC*NROWBLK];
__device__ float g_psq[NC*NROWBLK];
__device__ float g_scale[NC];
__device__ float g_shift[NC];

// ---------------- helpers ----------------
__device__ __forceinline__ float to_tf32(float x) {
    uint32_t o;
    asm("cvt.rna.tf32.f32 %0, %1;" : "=r"(o) : "f"(x));
    return __uint_as_float(o);
}
__device__ __forceinline__ uint32_t cvt_rna_u(uint32_t x) {
    uint32_t o;
    asm("cvt.rna.tf32.f32 %0, %1;" : "=r"(o) : "f"(__uint_as_float(x)));
    return o;
}
__device__ __forceinline__ void mma_tf32(float* d, const uint32_t* a, const uint32_t* b) {
    asm volatile("mma.sync.aligned.m16n8k8.row.col.f32.tf32.tf32.f32 "
        "{%0,%1,%2,%3}, {%4,%5,%6,%7}, {%8,%9}, {%0,%1,%2,%3};"
        : "+f"(d[0]), "+f"(d[1]), "+f"(d[2]), "+f"(d[3])
        : "r"(a[0]), "r"(a[1]), "r"(a[2]), "r"(a[3]), "r"(b[0]), "r"(b[1]));
}
__device__ __forceinline__ uint32_t smem_u32(const void* p) {
    uint32_t a;
    asm("{ .reg .u64 t; cvta.to.shared.u64 t, %1; cvt.u32.u64 %0, t; }" : "=r"(a) : "l"(p));
    return a;
}
__device__ __forceinline__ void cp16(uint32_t d, const void* s, bool pred) {
    int sz = pred ? 16 : 0;
    asm volatile("cp.async.cg.shared.global [%0], [%1], 16, %2;"
                 :: "r"(d), "l"(s), "r"(sz) : "memory");
}
__device__ __forceinline__ void cp_commit() {
    asm volatile("cp.async.commit_group;" ::: "memory");
}
#define CP_WAIT(n) asm volatile("cp.async.wait_group %0;" :: "n"(n) : "memory")

// ---------------- gap: per (b,c) spatial mean ----------------
__global__ void k_gap(const float* __restrict__ x) {
    int bc = blockIdx.x;
    int tid = threadIdx.x;
    __shared__ float red[256];
    const float4* p = (const float4*)(x + (size_t)bc * NL);
    float s = 0.f;
    for (int t = tid; t < NL/4; t += 256) { float4 v = p[t]; s += (v.x + v.y) + (v.z + v.w); }
    red[tid] = s; __syncthreads();
    for (int k = 128; k > 0; k >>= 1) { if (tid < k) red[tid] += red[tid+k]; __syncthreads(); }
    if (tid == 0) g_gap[bc >> 7][bc & 127] = red[0] * (1.0f / NL);
}

// ---------------- fold all weights into g_Bt (tf32-rounded) ----------------
__global__ void k_prepw(const float* __restrict__ wp,  const float* __restrict__ wout,
                        const float* __restrict__ wdw, const float* __restrict__ win,
                        const float* __restrict__ w2,  const float* __restrict__ b2,
                        const float* __restrict__ dwp) {
    int o = blockIdx.x, c = threadIdx.x;
    __shared__ float wps[NC], q[NC], red[NC];
    wps[c] = wp[o*NC + c];
    __syncthreads();
    float a = 0.f;
    #pragma unroll 8
    for (int t = 0; t < NC; t++) a = fmaf(wps[t], wout[t*NC + c], a);
    q[c] = a;
    __syncthreads();
    float a1 = 0.f, a2 = 0.f;
    #pragma unroll 8
    for (int s = 0; s < NC; s++) {
        float qs = q[s];
        float w1 = wdw[s*3 + 1], w02 = wdw[s*3 + 0] + wdw[s*3 + 2];
        float wi = win[s*NC + c];
        a1 = fmaf(qs * w1,  wi, a1);
        a2 = fmaf(qs * w02, wi, a2);
    }
    a1 += wps[c];                               // +Wp (raw-x path of y_diff)
    g_Bt[c*NC + o]          = to_tf32(a1);              // k 0..127:   B1 = Wp(M1+I)
    g_Bt[(NC + c)*NC + o]   = to_tf32(0.25f * a2);      // k 128..255: B2
    g_Bt[(2*NC + c)*NC + o] = to_tf32(dwp[0] * wps[c]); // k 256..383: B3 = dw*Wp
    if (c < NMID) {
        float s4 = 0.f;
        #pragma unroll 8
        for (int t = 0; t < NC; t++) s4 = fmaf(wps[t], w2[t*NMID + c], s4);
        g_Bt[(3*NC + c)*NC + o] = to_tf32(s4);          // k 384..415: Wp*W2
    }
    red[c] = wps[c] * b2[c];
    __syncthreads();
    for (int s = 64; s > 0; s >>= 1) { if (c < s) red[c] += red[c+s]; __syncthreads(); }
    if (c == 0) g_b2p[o] = red[0];
}

// ---------------- per-batch vectors: gap_n, c_k, u ----------------
__global__ void k_prep3(const float* __restrict__ wci, const float* __restrict__ wdwch,
                        const float* __restrict__ wco, const float* __restrict__ w1) {
    int b = blockIdx.x, c = threadIdx.x;
    __shared__ float red[NC], gs[NC], g2s[NC];
    float g = g_gap[b][c];
    red[c] = g * g; __syncthreads();
    for (int s = 64; s > 0; s >>= 1) { if (c < s) red[c] += red[c+s]; __syncthreads(); }
    float nrm = fmaxf(sqrtf(red[0]), 1e-12f);
    gs[c] = g / nrm;
    __syncthreads();
    float a = 0.f;
    #pragma unroll 8
    for (int j = 0; j < NC; j++) a = fmaf(gs[j], wco[j*NC + c], a);
    g2s[c] = a;
    __syncthreads();
    float s0 = 0.f, s1 = 0.f, s2 = 0.f;
    #pragma unroll 8
    for (int t = 0; t < NC; t++) {
        float wv = wci[t*NC + c] * g2s[t];
        s0 = fmaf(wv, wdwch[t*3 + 0], s0);
        s1 = fmaf(wv, wdwch[t*3 + 1], s1);
        s2 = fmaf(wv, wdwch[t*3 + 2], s2);
    }
    g_ck[b][0][c] = s0; g_ck[b][1][c] = s1; g_ck[b][2][c] = s2;
    if (c < NMID) {
        float s = 0.f;
        #pragma unroll 8
        for (int t = 0; t < NC; t++) s = fmaf(w1[c*NC + t], gs[t], s);
        g_u[b][c] = s;
    }
}

// ---------------- feature build: nsum/diff/silu rows to g_Fg ----------------
// grid = 8 batches x 16 tiles (1024 pos each); 256 threads; double-buffered x windows
#define TILE 1024
#define WPAD 132
#define WFLT (TILE + 2*WPAD)    // 1288 floats
#define WF4  (WFLT/4)           // 322

__global__ __launch_bounds__(256) void k_build(const float* __restrict__ x,
                                               const float* __restrict__ b1) {
    __shared__ __align__(16) float win[2][WFLT];
    __shared__ float cks[3*NC], us[NMID], b1s[NMID];
    const int tid = threadIdx.x;
    const int b = blockIdx.x >> 4;
    const int t = blockIdx.x & 15;
    const int tb = t << 10;
    const float* xb = x + (size_t)b * NC * NL;
    float* fgb = g_Fg + (size_t)b * NFROWS * NL;

    for (int q = tid; q < 3*NC; q += 256) cks[q] = (&g_ck[b][0][0])[q];
    if (tid < NMID) { us[tid] = g_u[b][tid]; b1s[tid] = b1[tid]; }

    // issue window for c=0
    {
        uint32_t d0 = smem_u32(&win[0][0]);
        const float* src = xb + tb - WPAD;
        for (int f = tid; f < WF4; f += 256) {
            int off = tb - WPAD + f*4;
            bool ok = (off >= 0) && (off + 4 <= NL);
            cp16(d0 + f*16, ok ? (src + f*4) : xb, ok);
        }
        cp_commit();
    }

    float v[4] = {0.f, 0.f, 0.f, 0.f};
    for (int c = 0; c < NC; c++) {
        if (c < NC-1) {
            uint32_t d0 = smem_u32(&win[(c+1)&1][0]);
            const float* src = xb + (size_t)(c+1)*NL + tb - WPAD;
            for (int f = tid; f < WF4; f += 256) {
                int off = tb - WPAD + f*4;
                bool ok = (off >= 0) && (off + 4 <= NL);
                cp16(d0 + f*16, ok ? (src + f*4) : xb, ok);
            }
            cp_commit();
            CP_WAIT(1);
        } else {
            CP_WAIT(0);
        }
        __syncthreads();
        const float* w = win[c&1];
        const float* xc_row = xb + (size_t)c*NL;
        float k0 = cks[c], k1 = cks[NC+c], k2 = cks[2*NC+c];
        #pragma unroll
        for (int r = 0; r < 4; r++) {
            int pl = tid + (r << 8);
            int gpos = tb + pl;
            int q = pl + WPAD;
            int ii = gpos >> 7, jj = gpos & 127;
            float xc = w[q];
            float l  = w[q-1];         // window zero-filled at batch edges
            float rr = w[q+1];
            float u  = (ii > 0)   ? w[q-128] : ((jj > 0)   ? xc_row[127*NW + jj - 1] : 0.f);
            float d  = (ii < 127) ? w[q+128] : ((jj < 127) ? xc_row[jj + 1]          : 0.f);
            float lr = (jj > 0)   ? w[q-1]   : w[q+1];
            float rt = (jj < 127) ? w[q+1]   : w[q-1];
            float ur = (ii > 0)   ? w[q-128] : w[q+128];
            float dr = (ii < 127) ? w[q+128] : w[q-128];
            fgb[(size_t)c*NL + gpos]        = to_tf32((l + rr) + (u + d));
            fgb[(size_t)(NC + c)*NL + gpos] =
                to_tf32(0.25f * ((fabsf(xc-lr) + fabsf(xc-rt)) + (fabsf(xc-ur) + fabsf(xc-dr))));
            v[r] = fmaf(k0, l, fmaf(k1, xc, fmaf(k2, rr, v[r])));
        }
        __syncthreads();
    }

    // silu rows 256..287 of fgb
    for (int m = 0; m < NMID; m++) {
        float um = us[m], bm = b1s[m];
        #pragma unroll
        for (int r = 0; r < 4; r++) {
            float z = fmaf(um, v[r], bm);
            float sv = z / (1.f + __expf(-z));
            fgb[(size_t)(2*NC + m)*NL + tb + tid + (r << 8)] = to_tf32(sv);
        }
    }
}

// ---------------- GEMM: D[o][pos] = sum_k Bt[k][o]*F[k][pos], 3-stage cp.async ----------------
// grid = 1024 (8 b x 128 pos-tiles of 128); dyn smem = 3 stages x (A 16KB + B 16KB)
#define GSMEM (3*8192*4)

__global__ __launch_bounds__(256, 2) void k_gemm(const float* __restrict__ x) {
    extern __shared__ __align__(16) float sm[];
    const int tid = threadIdx.x;
    const int b = blockIdx.x >> 7;
    const int pt = blockIdx.x & 127;
    const int posb = pt << 7;
    const float* xb  = x + (size_t)b * NC * NL + posb;
    const float* fgb = g_Fg + (size_t)b * NFROWS * NL + posb;

    auto issueP = [&](int p, int st) {
        int k0 = p * 32;
        const float* bsrc = (k0 < NC) ? (xb + (size_t)k0 * NL) : (fgb + (size_t)(k0 - NC) * NL);
        const float* asrc = g_Bt + k0 * NC;
        uint32_t ab = smem_u32(sm + st * 8192);
        uint32_t bb = ab + 16384;
        for (int f = tid; f < 1024; f += 256) {
            int kr = f >> 5, j4 = f & 31;
            int sw = kr*32 + (j4 ^ ((kr & 3) << 1));
            cp16(ab + sw*16, asrc + kr*NC + (j4 << 2), true);
            cp16(bb + sw*16, bsrc + (size_t)kr*NL + (j4 << 2), true);
        }
        cp_commit();
    };
    issueP(0, 0); issueP(1, 1); issueP(2, 2);

    const int lane = tid & 31, g = lane >> 2, tg = lane & 3;
    const int w = tid >> 5, mbase = (w >> 2) * 64, nbase = (w & 3) * 32;
    const int swa = tg << 3;
    float dacc[4][4][4];
    #pragma unroll
    for (int mt = 0; mt < 4; mt++)
        #pragma unroll
        for (int nt = 0; nt < 4; nt++)
            #pragma unroll
            for (int q = 0; q < 4; q++) dacc[mt][nt][q] = 0.f;

    int st = 0;
    for (int p = 0; p < NPAN; p++) {
        if (p < NPAN-2) { CP_WAIT(2); } else if (p == NPAN-2) { CP_WAIT(1); } else { CP_WAIT(0); }
        __syncthreads();
        const uint32_t* As = (const uint32_t*)(sm + st * 8192);
        const uint32_t* Fu = As + 4096;
        #pragma unroll
        for (int ks = 0; ks < 4; ks++) {
            const int kr = ks * 8;
            uint32_t af[4][4], bf[4][2];
            #pragma unroll
            for (int nt = 0; nt < 4; nt++) {
                int n = nbase + nt*8 + g;
                bf[nt][0] = cvt_rna_u(Fu[(kr + tg)*128 + (n ^ swa)]);
                bf[nt][1] = cvt_rna_u(Fu[(kr + tg + 4)*128 + (n ^ swa)]);
            }
            #pragma unroll
            for (int mt = 0; mt < 4; mt++) {
                int o = mbase + mt*16 + g;
                af[mt][0] = As[(kr + tg)*128 + (o ^ swa)];
                af[mt][1] = As[(kr + tg)*128 + ((o+8) ^ swa)];
                af[mt][2] = As[(kr + tg + 4)*128 + (o ^ swa)];
                af[mt][3] = As[(kr + tg + 4)*128 + ((o+8) ^ swa)];
            }
            #pragma unroll
            for (int mt = 0; mt < 4; mt++)
                #pragma unroll
                for (int nt = 0; nt < 4; nt++)
                    mma_tf32(dacc[mt][nt], af[mt], bf[nt]);
        }
        __syncthreads();
        if (p + 3 < NPAN) issueP(p + 3, st);
        st = (st == 2) ? 0 : st + 1;
    }

    // ---- epilogue: bias, y2 store, BN partials ----
    float* sred = sm;      // reuse stage 0 (all compute done)
    #pragma unroll
    for (int mt = 0; mt < 4; mt++) {
        int o0 = mbase + mt*16 + g, o1 = o0 + 8;
        float bb0 = g_b2p[o0], bb1 = g_b2p[o1];
        float* row0 = &g_y2[(size_t)(b*NC + o0) * NL + posb];
        float* row1 = &g_y2[(size_t)(b*NC + o1) * NL + posb];
        float s0 = 0.f, q0 = 0.f, s1 = 0.f, q1 = 0.f;
        #pragma unroll
        for (int nt = 0; nt < 4; nt++) {
            float v0 = dacc[mt][nt][0] + bb0, v1 = dacc[mt][nt][1] + bb0;
            float v2 = dacc[mt][nt][2] + bb1, v3 = dacc[mt][nt][3] + bb1;
            int j = nbase + nt*8 + 2*tg;
            *(float2*)(row0 + j) = make_float2(v0, v1);
            *(float2*)(row1 + j) = make_float2(v2, v3);
            s0 += v0 + v1; q0 = fmaf(v0, v0, q0); q0 = fmaf(v1, v1, q0);
            s1 += v2 + v3; q1 = fmaf(v2, v2, q1); q1 = fmaf(v3, v3, q1);
        }
        s0 += __shfl_xor_sync(0xffffffff, s0, 1); s0 += __shfl_xor_sync(0xffffffff, s0, 2);
        q0 += __shfl_xor_sync(0xffffffff, q0, 1); q0 += __shfl_xor_sync(0xffffffff, q0, 2);
        s1 += __shfl_xor_sync(0xffffffff, s1, 1); s1 += __shfl_xor_sync(0xffffffff, s1, 2);
        q1 += __shfl_xor_sync(0xffffffff, q1, 1); q1 += __shfl_xor_sync(0xffffffff, q1, 2);
        if (tg == 0) {
            int nwq = w & 3;
            sred[o0*4 + nwq] = s0; sred[512 + o0*4 + nwq] = q0;
            sred[o1*4 + nwq] = s1; sred[512 + o1*4 + nwq] = q1;
        }
    }
    __syncthreads();
    if (tid < NC) {
        float s = 0.f, q = 0.f;
        #pragma unroll
        for (int t = 0; t < 4; t++) { s += sred[tid*4 + t]; q += sred[512 + tid*4 + t]; }
        g_psum[tid*NROWBLK + blockIdx.x] = s;
        g_psq [tid*NROWBLK + blockIdx.x] = q;
    }
}

// ---------------- BN stats ----------------
__global__ void k_bnstat(const float* __restrict__ gamma, const float* __restrict__ beta) {
    int c = blockIdx.x, tid = threadIdx.x;
    __shared__ float s1[256], s2[256];
    float a = 0.f, q = 0.f;
    for (int t = tid; t < NROWBLK; t += 256) { a += g_psum[c*NROWBLK + t]; q += g_psq[c*NROWBLK + t]; }
    s1[tid] = a; s2[tid] = q; __syncthreads();
    for (int s = 128; s > 0; s >>= 1) {
        if (tid < s) { s1[tid] += s1[tid+s]; s2[tid] += s2[tid+s]; }
        __syncthreads();
    }
    if (tid == 0) {
        const float invN = 1.0f / (float)(NB * NL);
        float mu  = s1[0] * invN;
        float var = s2[0] * invN - mu * mu;
        float rs  = rsqrtf(var + 1e-5f);
        float sc  = gamma[c] * rs;
        g_scale[c] = sc;
        g_shift[c] = beta[c] - mu * sc;
    }
}

// ---------------- normalize ----------------
__global__ void k_norm(float* __restrict__ out) {
    int idx = blockIdx.x * blockDim.x + threadIdx.x;
    float4 v = ((const float4*)g_y2)[idx];
    int c = (idx >> 12) & 127;
    float sc = g_scale[c], sh = g_shift[c];
    v.x = fmaf(v.x, sc, sh); v.y = fmaf(v.y, sc, sh);
    v.z = fmaf(v.z, sc, sh); v.w = fmaf(v.w, sc, sh);
    ((float4*)out)[idx] = v;
}

// ---------------- launcher ----------------
extern "C" void kernel_launch(void* const* d_in, const int* in_sizes, int n_in,
                              void* d_out, int out_size) {
    const float* x            = (const float*)d_in[0];
    const float* w_spatial_in = (const float*)d_in[1];
    const float* w_dw_spatial = (const float*)d_in[2];
    const float* w_spatial_out= (const float*)d_in[3];
    const float* w_ch_in      = (const float*)d_in[4];
    const float* w_ch_dw      = (const float*)d_in[5];
    const float* w_ch_out     = (const float*)d_in[6];
    const float* w_mlp1       = (const float*)d_in[7];
    const float* b_mlp1       = (const float*)d_in[8];
    const float* w_mlp2       = (const float*)d_in[9];
    const float* b_mlp2       = (const float*)d_in[10];
    const float* diff_weight  = (const float*)d_in[11];
    const float* bn_gamma     = (const float*)d_in[12];
    const float* bn_beta      = (const float*)d_in[13];
    const float* w_out_proj   = (const float*)d_in[14];
    float* out = (float*)d_out;

    cudaFuncSetAttribute(k_gemm, cudaFuncAttributeMaxDynamicSharedMemorySize, GSMEM);

    k_prepw<<<NC, NC>>>(w_out_proj, w_spatial_out, w_dw_spatial, w_spatial_in,
                        w_mlp2, b_mlp2, diff_weight);
    k_gap  <<<NB*NC, 256>>>(x);
    k_prep3<<<NB, NC>>>(w_ch_in, w_ch_dw, w_ch_out, w_mlp1);
    k_build<<<NB*16, 256>>>(x, b_mlp1);
    k_gemm <<<NROWBLK, 256, GSMEM>>>(x);
    k_bnstat<<<NC, 256>>>(bn_gamma, bn_beta);
    k_norm <<<NTOT/4/256, 256>>>(out);
}

// round 5
// speedup vs baseline: 2.8517x; 1.0341x over previous
#include <cuda_runtime.h>
#include <math.h>
#include <stdint.h>

#define NB 8
#define NC 128
#define NH 128
#define NW 128
#define NL (NH*NW)          // 16384
#define NMID 32
#define KTOT 416
#define NROWBLK 1024
#define NTOT (NB*NC*NL)     // 16777216

// ---------------- device scratch ----------------
__device__ float g_y2[NTOT];
__device__ __align__(16) float g_silu[(size_t)NB*NMID*NL];   // 16MB pre-rounded silu rows
__device__ float g_gap[NB][NC];
__device__ __align__(16) float g_Bt[KTOT*NC];   // folded weights [k'][o], K reordered per 32-ch groups
__device__ float g_ck[NB][3][NC];
__device__ float g_u[NB][NMID];
__device__ float g_b2p[NC];
__device__ float g_psum[NC*NROWBLK];
__device__ float g_psq[NC*NROWBLK];
__device__ float g_scale[NC];
__device__ float g_shift[NC];

// ---------------- helpers ----------------
__device__ __forceinline__ float to_tf32(float x) {
    uint32_t o;
    asm("cvt.rna.tf32.f32 %0, %1;" : "=r"(o) : "f"(x));
    return __uint_as_float(o);
}
__device__ __forceinline__ uint32_t cvt_rna_u(uint32_t x) {
    uint32_t o;
    asm("cvt.rna.tf32.f32 %0, %1;" : "=r"(o) : "f"(__uint_as_float(x)));
    return o;
}
__device__ __forceinline__ void mma_tf32(float* d, const uint32_t* a, const uint32_t* b) {
    asm volatile("mma.sync.aligned.m16n8k8.row.col.f32.tf32.tf32.f32 "
        "{%0,%1,%2,%3}, {%4,%5,%6,%7}, {%8,%9}, {%0,%1,%2,%3};"
        : "+f"(d[0]), "+f"(d[1]), "+f"(d[2]), "+f"(d[3])
        : "r"(a[0]), "r"(a[1]), "r"(a[2]), "r"(a[3]), "r"(b[0]), "r"(b[1]));
}
__device__ __forceinline__ uint32_t smem_u32(const void* p) {
    uint32_t a;
    asm("{ .reg .u64 t; cvta.to.shared.u64 t, %1; cvt.u32.u64 %0, t; }" : "=r"(a) : "l"(p));
    return a;
}
// pred=false -> zero-fill (src-size 0)
__device__ __forceinline__ void cp16(uint32_t d, const void* s, bool pred) {
    int sz = pred ? 16 : 0;
    asm volatile("cp.async.cg.shared.global [%0], [%1], 16, %2;"
                 :: "r"(d), "l"(s), "r"(sz) : "memory");
}
__device__ __forceinline__ void cp_commit() {
    asm volatile("cp.async.commit_group;" ::: "memory");
}
#define CP_WAIT(n) asm volatile("cp.async.wait_group %0;" :: "n"(n) : "memory")

// ---------------- gap ----------------
__global__ void k_gap(const float* __restrict__ x) {
    int bc = blockIdx.x;
    int tid = threadIdx.x;
    __shared__ float red[256];
    const float4* p = (const float4*)(x + (size_t)bc * NL);
    float s = 0.f;
    for (int t = tid; t < NL/4; t += 256) { float4 v = p[t]; s += (v.x + v.y) + (v.z + v.w); }
    red[tid] = s; __syncthreads();
    for (int k = 128; k > 0; k >>= 1) { if (tid < k) red[tid] += red[tid+k]; __syncthreads(); }
    if (tid == 0) g_gap[bc >> 7][bc & 127] = red[0] * (1.0f / NL);
}

// ---------------- fold weights into g_Bt (K reordered: per g: x|nsum|diff; then silu) ----------------
__global__ void k_prepw(const float* __restrict__ wp,  const float* __restrict__ wout,
                        const float* __restrict__ wdw, const float* __restrict__ win,
                        const float* __restrict__ w2,  const float* __restrict__ b2,
                        const float* __restrict__ dwp) {
    int o = blockIdx.x, c = threadIdx.x;
    __shared__ float wps[NC], q[NC], red[NC];
    wps[c] = wp[o*NC + c];
    __syncthreads();
    float a = 0.f;
    #pragma unroll 8
    for (int t = 0; t < NC; t++) a = fmaf(wps[t], wout[t*NC + c], a);
    q[c] = a;
    __syncthreads();
    float a1 = 0.f, a2 = 0.f;
    #pragma unroll 8
    for (int s = 0; s < NC; s++) {
        float qs = q[s];
        float w1 = wdw[s*3 + 1], w02 = wdw[s*3 + 0] + wdw[s*3 + 2];
        float wi = win[s*NC + c];
        a1 = fmaf(qs * w1,  wi, a1);
        a2 = fmaf(qs * w02, wi, a2);
    }
    a1 += wps[c];                               // +Wp (raw-x path of y_diff)
    int gq = c >> 5, lr = c & 31;
    g_Bt[(96*gq + lr)*NC + o]      = to_tf32(a1);              // x row
    g_Bt[(96*gq + 32 + lr)*NC + o] = to_tf32(0.25f * a2);      // nsum row
    g_Bt[(96*gq + 64 + lr)*NC + o] = to_tf32(dwp[0] * wps[c]); // diff row
    if (c < NMID) {
        float s4 = 0.f;
        #pragma unroll 8
        for (int t = 0; t < NC; t++) s4 = fmaf(wps[t], w2[t*NMID + c], s4);
        g_Bt[(384 + c)*NC + o] = to_tf32(s4);                  // silu row
    }
    red[c] = wps[c] * b2[c];
    __syncthreads();
    for (int s = 64; s > 0; s >>= 1) { if (c < s) red[c] += red[c+s]; __syncthreads(); }
    if (c == 0) g_b2p[o] = red[0];
}

// ---------------- per-batch vectors: gap_n, c_k, u ----------------
__global__ void k_prep3(const float* __restrict__ wci, const float* __restrict__ wdwch,
                        const float* __restrict__ wco, const float* __restrict__ w1) {
    int b = blockIdx.x, c = threadIdx.x;
    __shared__ float red[NC], gs[NC], g2s[NC];
    float g = g_gap[b][c];
    red[c] = g * g; __syncthreads();
    for (int s = 64; s > 0; s >>= 1) { if (c < s) red[c] += red[c+s]; __syncthreads(); }
    float nrm = fmaxf(sqrtf(red[0]), 1e-12f);
    gs[c] = g / nrm;
    __syncthreads();
    float a = 0.f;
    #pragma unroll 8
    for (int j = 0; j < NC; j++) a = fmaf(gs[j], wco[j*NC + c], a);
    g2s[c] = a;
    __syncthreads();
    float s0 = 0.f, s1 = 0.f, s2 = 0.f;
    #pragma unroll 8
    for (int t = 0; t < NC; t++) {
        float wv = wci[t*NC + c] * g2s[t];
        s0 = fmaf(wv, wdwch[t*3 + 0], s0);
        s1 = fmaf(wv, wdwch[t*3 + 1], s1);
        s2 = fmaf(wv, wdwch[t*3 + 2], s2);
    }
    g_ck[b][0][c] = s0; g_ck[b][1][c] = s1; g_ck[b][2][c] = s2;
    if (c < NMID) {
        float s = 0.f;
        #pragma unroll 8
        for (int t = 0; t < NC; t++) s = fmaf(w1[c*NC + t], gs[t], s);
        g_u[b][c] = s;
    }
}

// ---------------- v reduction + silu rows ----------------
// grid = 8 b x 64 tiles of 256 pos; 256 threads, 1 pos each; double-buffered x windows
__global__ __launch_bounds__(256) void k_vred(const float* __restrict__ x,
                                              const float* __restrict__ b1) {
    __shared__ __align__(16) float win[2][272];
    __shared__ float cks[3*NC], us[NMID], b1s[NMID];
    const int tid = threadIdx.x;
    const int b = blockIdx.x >> 6;
    const int tb = (blockIdx.x & 63) << 8;
    const float* xb = x + (size_t)b * NC * NL;

    for (int q = tid; q < 3*NC; q += 256) cks[q] = (&g_ck[b][0][0])[q];
    if (tid < NMID) { us[tid] = g_u[b][tid]; b1s[tid] = b1[tid]; }

    auto issue = [&](int c, int buf) {
        uint32_t d = smem_u32(&win[buf][0]);
        if (tid < 68) {
            int off = tb - 8 + tid*4;
            bool ok = (off >= 0) && (off + 4 <= NL);
            const float* src = xb + (size_t)c*NL + off;
            cp16(d + tid*16, ok ? src : xb, ok);
        }
        cp_commit();
    };
    issue(0, 0);
    float v = 0.f;
    for (int c = 0; c < NC; c++) {
        if (c < NC-1) { issue(c+1, (c+1)&1); CP_WAIT(1); } else { CP_WAIT(0); }
        __syncthreads();
        const float* w = win[c&1];
        v = fmaf(cks[c], w[7+tid],
            fmaf(cks[NC+c], w[8+tid],
            fmaf(cks[2*NC+c], w[9+tid], v)));
        __syncthreads();
    }
    float* dst = g_silu + (size_t)b * NMID * NL + tb + tid;
    #pragma unroll 4
    for (int m = 0; m < NMID; m++) {
        float z = fmaf(us[m], v, b1s[m]);
        dst[(size_t)m * NL] = to_tf32(z / (1.f + __expf(-z)));
    }
}

// ---------------- GEMM with in-kernel stencil panels ----------------
// block = (b, image row i); K panels: g=0..3: [x_g, nsum_g, diff_g], then silu
// smem: Wm1/Wc/Wp1 16KB each, B0 16KB, A 2x16KB  => 96KB
#define GSMEM (24576*4)

__global__ __launch_bounds__(256, 2) void k_gemm(const float* __restrict__ x) {
    extern __shared__ __align__(16) float sm[];
    float* Wm1 = sm;
    float* Wc  = sm + 4096;
    float* Wp1 = sm + 8192;
    float* B0  = sm + 12288;
    float* Apan= sm + 16384;     // 2 x 4096
    const int tid = threadIdx.x;
    const int b = blockIdx.x >> 7;
    const int i = blockIdx.x & 127;
    const int posb = i * NW;
    const float* xb = x + (size_t)b * NC * NL;

    const uint32_t wm1a = smem_u32(Wm1), wca = smem_u32(Wc), wp1a = smem_u32(Wp1);
    const uint32_t b0a = smem_u32(B0), apa = smem_u32(Apan);

    auto issueW = [&](int g) {
        const float* base = xb + (size_t)(g*32) * NL + posb;
        #pragma unroll
        for (int r = 0; r < 4; r++) {
            int f = tid + r*256;
            int ch = f >> 5, j4 = f & 31;
            int sw = (ch*32 + (j4 ^ ((ch&3)<<1))) * 16;
            const float* rsrc = base + (size_t)ch*NL + (j4 << 2);
            cp16(wm1a + sw, (i > 0)   ? (rsrc - NW) : xb, i > 0);
            cp16(wca  + sw, rsrc, true);
            cp16(wp1a + sw, (i < 127) ? (rsrc + NW) : xb, i < 127);
        }
        cp_commit();
    };
    auto issueA = [&](int p) {
        const float* asrc = g_Bt + p * 32 * NC;
        uint32_t ab = apa + (p & 1) * 16384;
        #pragma unroll
        for (int r = 0; r < 4; r++) {
            int f = tid + r*256;
            int kr = f >> 5, j4 = f & 31;
            cp16(ab + (kr*32 + (j4 ^ ((kr&3)<<1)))*16, asrc + kr*NC + (j4 << 2), true);
        }
        cp_commit();
    };
    auto issueSilu = [&]() {
        const float* ssrc = g_silu + (size_t)b * NMID * NL + posb;
        #pragma unroll
        for (int r = 0; r < 4; r++) {
            int f = tid + r*256;
            int ch = f >> 5, j4 = f & 31;
            cp16(wca + (ch*32 + (j4 ^ ((ch&3)<<1)))*16, ssrc + (size_t)ch*NL + (j4 << 2), true);
        }
        cp_commit();
    };

    const int lane = tid & 31, gq = lane >> 2, tg = lane & 3;
    const int w = tid >> 5, mbase = (w >> 2) * 64, nbase = (w & 3) * 32;
    const int swa = tg << 3;
    float dacc[4][4][4];
    #pragma unroll
    for (int mt = 0; mt < 4; mt++)
        #pragma unroll
        for (int nt = 0; nt < 4; nt++)
            #pragma unroll
            for (int qq = 0; qq < 4; qq++) dacc[mt][nt][qq] = 0.f;

    auto mmaPanel = [&](const uint32_t* As, const uint32_t* Fu, bool cvt) {
        #pragma unroll
        for (int ks = 0; ks < 4; ks++) {
            const int kr = ks * 8;
            uint32_t af[4][4], bf[4][2];
            #pragma unroll
            for (int nt = 0; nt < 4; nt++) {
                int n = nbase + nt*8 + gq;
                uint32_t v0 = Fu[(kr + tg)*128 + (n ^ swa)];
                uint32_t v1 = Fu[(kr + tg + 4)*128 + (n ^ swa)];
                bf[nt][0] = cvt ? cvt_rna_u(v0) : v0;
                bf[nt][1] = cvt ? cvt_rna_u(v1) : v1;
            }
            #pragma unroll
            for (int mt = 0; mt < 4; mt++) {
                int o = mbase + mt*16 + gq;
                af[mt][0] = As[(kr + tg)*128 + (o ^ swa)];
                af[mt][1] = As[(kr + tg)*128 + ((o+8) ^ swa)];
                af[mt][2] = As[(kr + tg + 4)*128 + (o ^ swa)];
                af[mt][3] = As[(kr + tg + 4)*128 + ((o+8) ^ swa)];
            }
            #pragma unroll
            for (int mt = 0; mt < 4; mt++)
                #pragma unroll
                for (int nt = 0; nt < 4; nt++)
                    mma_tf32(dacc[mt][nt], af[mt], bf[nt]);
        }
    };

    auto computeNsum = [&](int g) {
        int j = tid & 127, ch0 = (tid >> 7) * 16;
        #pragma unroll 4
        for (int ch = ch0; ch < ch0 + 16; ch++) {
            int sw = (ch & 3) << 3;
            float wl = (j > 0)   ? Wc[ch*128 + ((j-1) ^ sw)] : Wm1[ch*128 + (127 ^ sw)];
            float wr = (j < 127) ? Wc[ch*128 + ((j+1) ^ sw)] : Wp1[ch*128 + (0 ^ sw)];
            float wu, wd;
            if (i > 0) wu = Wm1[ch*128 + (j ^ sw)];
            else wu = (j > 0) ? __ldg(xb + (size_t)(g*32+ch)*NL + 127*NW + j - 1) : 0.f;
            if (i < 127) wd = Wp1[ch*128 + (j ^ sw)];
            else wd = (j < 127) ? __ldg(xb + (size_t)(g*32+ch)*NL + j + 1) : 0.f;
            B0[ch*128 + (j ^ sw)] = to_tf32((wl + wr) + (wu + wd));
        }
    };
    auto computeDiff = [&]() {
        int j = tid & 127, ch0 = (tid >> 7) * 16;
        #pragma unroll 4
        for (int ch = ch0; ch < ch0 + 16; ch++) {
            int sw = (ch & 3) << 3;
            float xc = Wc[ch*128 + (j ^ sw)];
            float lr = (j > 0)   ? Wc[ch*128 + ((j-1) ^ sw)] : Wc[ch*128 + (1 ^ sw)];
            float rr = (j < 127) ? Wc[ch*128 + ((j+1) ^ sw)] : Wc[ch*128 + (126 ^ sw)];
            float ur = (i > 0)   ? Wm1[ch*128 + (j ^ sw)] : Wp1[ch*128 + (j ^ sw)];
            float dr = (i < 127) ? Wp1[ch*128 + (j ^ sw)] : Wm1[ch*128 + (j ^ sw)];
            B0[ch*128 + (j ^ sw)] =
                to_tf32(0.25f * ((fabsf(xc-lr) + fabsf(xc-rr)) + (fabsf(xc-ur) + fabsf(xc-dr))));
        }
    };

    issueW(0);
    issueA(0);
    for (int g = 0; g < 4; g++) {
        const uint32_t* A0p = (const uint32_t*)(Apan + ((3*g) & 1) * 4096);
        const uint32_t* A1p = (const uint32_t*)(Apan + ((3*g+1) & 1) * 4096);
        const uint32_t* A2p = (const uint32_t*)(Apan + ((3*g+2) & 1) * 4096);
        CP_WAIT(0); __syncthreads();                 // W(g), A(3g) ready
        mmaPanel(A0p, (const uint32_t*)Wc, true);    // x panel
        issueA(3*g + 1);
        computeNsum(g);
        CP_WAIT(0); __syncthreads();                 // A(3g+1) + B0 ready
        mmaPanel(A1p, (const uint32_t*)B0, false);   // nsum panel
        issueA(3*g + 2);
        __syncthreads();                             // all warps done reading B0
        computeDiff();
        __syncthreads();                             // B0 + window reads done
        if (g < 3) issueW(g + 1); else issueSilu();
        CP_WAIT(1); __syncthreads();                 // A(3g+2) ready (W/silu pending)
        mmaPanel(A2p, (const uint32_t*)B0, false);   // diff panel
        if (g < 3) issueA(3*g + 3); else issueA(12);
    }
    CP_WAIT(0); __syncthreads();                     // silu B + A12 ready
    mmaPanel((const uint32_t*)(Apan + 0), (const uint32_t*)Wc, true);  // silu panel (stage 12&1=0)
    __syncthreads();                                 // done reading Apan -> reuse as sred

    // ---- epilogue: bias, y2 store, BN partials ----
    float* sred = Apan;
    #pragma unroll
    for (int mt = 0; mt < 4; mt++) {
        int o0 = mbase + mt*16 + gq, o1 = o0 + 8;
        float bb0 = g_b2p[o0], bb1 = g_b2p[o1];
        float* row0 = &g_y2[(size_t)(b*NC + o0) * NL + posb];
        float* row1 = &g_y2[(size_t)(b*NC + o1) * NL + posb];
        float s0 = 0.f, q0 = 0.f, s1 = 0.f, q1 = 0.f;
        #pragma unroll
        for (int nt = 0; nt < 4; nt++) {
            float v0 = dacc[mt][nt][0] + bb0, v1 = dacc[mt][nt][1] + bb0;
            float v2 = dacc[mt][nt][2] + bb1, v3 = dacc[mt][nt][3] + bb1;
            int j = nbase + nt*8 + 2*tg;
            *(float2*)(row0 + j) = make_float2(v0, v1);
            *(float2*)(row1 + j) = make_float2(v2, v3);
            s0 += v0 + v1; q0 = fmaf(v0, v0, q0); q0 = fmaf(v1, v1, q0);
            s1 += v2 + v3; q1 = fmaf(v2, v2, q1); q1 = fmaf(v3, v3, q1);
        }
        s0 += __shfl_xor_sync(0xffffffff, s0, 1); s0 += __shfl_xor_sync(0xffffffff, s0, 2);
        q0 += __shfl_xor_sync(0xffffffff, q0, 1); q0 += __shfl_xor_sync(0xffffffff, q0, 2);
        s1 += __shfl_xor_sync(0xffffffff, s1, 1); s1 += __shfl_xor_sync(0xffffffff, s1, 2);
        q1 += __shfl_xor_sync(0xffffffff, q1, 1); q1 += __shfl_xor_sync(0xffffffff, q1, 2);
        if (tg == 0) {
            int nwq = w & 3;
            sred[o0*4 + nwq] = s0; sred[512 + o0*4 + nwq] = q0;
            sred[o1*4 + nwq] = s1; sred[512 + o1*4 + nwq] = q1;
        }
    }
    __syncthreads();
    if (tid < NC) {
        float s = 0.f, q = 0.f;
        #pragma unroll
        for (int t = 0; t < 4; t++) { s += sred[tid*4 + t]; q += sred[512 + tid*4 + t]; }
        g_psum[tid*NROWBLK + blockIdx.x] = s;
        g_psq [tid*NROWBLK + blockIdx.x] = q;
    }
}

// ---------------- BN stats ----------------
__global__ void k_bnstat(const float* __restrict__ gamma, const float* __restrict__ beta) {
    int c = blockIdx.x, tid = threadIdx.x;
    __shared__ float s1[256], s2[256];
    float a = 0.f, q = 0.f;
    for (int t = tid; t < NROWBLK; t += 256) { a += g_psum[c*NROWBLK + t]; q += g_psq[c*NROWBLK + t]; }
    s1[tid] = a; s2[tid] = q; __syncthreads();
    for (int s = 128; s > 0; s >>= 1) {
        if (tid < s) { s1[tid] += s1[tid+s]; s2[tid] += s2[tid+s]; }
        __syncthreads();
    }
    if (tid == 0) {
        const float invN = 1.0f / (float)(NB * NL);
        float mu  = s1[0] * invN;
        float var = s2[0] * invN - mu * mu;
        float rs  = rsqrtf(var + 1e-5f);
        float sc  = gamma[c] * rs;
        g_scale[c] = sc;
        g_shift[c] = beta[c] - mu * sc;
    }
}

// ---------------- normalize ----------------
__global__ void k_norm(float* __restrict__ out) {
    int idx = blockIdx.x * blockDim.x + threadIdx.x;
    float4 v = ((const float4*)g_y2)[idx];
    int c = (idx >> 12) & 127;
    float sc = g_scale[c], sh = g_shift[c];
    v.x = fmaf(v.x, sc, sh); v.y = fmaf(v.y, sc, sh);
    v.z = fmaf(v.z, sc, sh); v.w = fmaf(v.w, sc, sh);
    ((float4*)out)[idx] = v;
}

// ---------------- launcher ----------------
extern "C" void kernel_launch(void* const* d_in, const int* in_sizes, int n_in,
                              void* d_out, int out_size) {
    const float* x            = (const float*)d_in[0];
    const float* w_spatial_in = (const float*)d_in[1];
    const float* w_dw_spatial = (const float*)d_in[2];
    const float* w_spatial_out= (const float*)d_in[3];
    const float* w_ch_in      = (const float*)d_in[4];
    const float* w_ch_dw      = (const float*)d_in[5];
    const float* w_ch_out     = (const float*)d_in[6];
    const float* w_mlp1       = (const float*)d_in[7];
    const float* b_mlp1       = (const float*)d_in[8];
    const float* w_mlp2       = (const float*)d_in[9];
    const float* b_mlp2       = (const float*)d_in[10];
    const float* diff_weight  = (const float*)d_in[11];
    const float* bn_gamma     = (const float*)d_in[12];
    const float* bn_beta      = (const float*)d_in[13];
    const float* w_out_proj   = (const float*)d_in[14];
    float* out = (float*)d_out;

    cudaFuncSetAttribute(k_gemm, cudaFuncAttributeMaxDynamicSharedMemorySize, GSMEM);

    k_prepw<<<NC, NC>>>(w_out_proj, w_spatial_out, w_dw_spatial, w_spatial_in,
                        w_mlp2, b_mlp2, diff_weight);
    k_gap  <<<NB*NC, 256>>>(x);
    k_prep3<<<NB, NC>>>(w_ch_in, w_ch_dw, w_ch_out, w_mlp1);
    k_vred <<<NB*64, 256>>>(x, b_mlp1);
    k_gemm <<<NROWBLK, 256, GSMEM>>>(x);
    k_bnstat<<<NC, 256>>>(bn_gamma, bn_beta);
    k_norm <<<NTOT/4/256, 256>>>(out);
}

// round 6
// speedup vs baseline: 3.0934x; 1.0847x over previous
#include <cuda_runtime.h>
#include <math.h>
#include <stdint.h>

#define NB 8
#define NC 128
#define NH 128
#define NW 128
#define NL (NH*NW)          // 16384
#define NMID 32
#define KTOT 416
#define NPAN 13
#define NFROWS 288          // nsum(128) + diff(128) + silu(32)
#define NROWBLK 1024
#define NTOT (NB*NC*NL)

// ---------------- device scratch ----------------
__device__ float g_y2[NTOT];
__device__ __align__(16) float g_Fg[(size_t)NB*NFROWS*NL];   // feature rows (tf32-rounded)
__device__ float g_gap[NB][NC];
__device__ __align__(16) float g_Bt[KTOT*NC];   // folded weights [k][o], tf32-rounded
__device__ float g_ck[NB][3][NC];
__device__ float g_u[NB][NMID];
__device__ float g_b2p[NC];
__device__ float g_psum[NC*NROWBLK];
__device__ float g_psq[NC*NROWBLK];
__device__ float g_scale[NC];
__device__ float g_shift[NC];

// ---------------- helpers ----------------
__device__ __forceinline__ float to_tf32(float x) {
    uint32_t o;
    asm("cvt.rna.tf32.f32 %0, %1;" : "=r"(o) : "f"(x));
    return __uint_as_float(o);
}
__device__ __forceinline__ uint32_t cvt_rna_u(uint32_t x) {
    uint32_t o;
    asm("cvt.rna.tf32.f32 %0, %1;" : "=r"(o) : "f"(__uint_as_float(x)));
    return o;
}
__device__ __forceinline__ void mma_tf32(float* d, const uint32_t* a, const uint32_t* b) {
    asm volatile("mma.sync.aligned.m16n8k8.row.col.f32.tf32.tf32.f32 "
        "{%0,%1,%2,%3}, {%4,%5,%6,%7}, {%8,%9}, {%0,%1,%2,%3};"
        : "+f"(d[0]), "+f"(d[1]), "+f"(d[2]), "+f"(d[3])
        : "r"(a[0]), "r"(a[1]), "r"(a[2]), "r"(a[3]), "r"(b[0]), "r"(b[1]));
}
__device__ __forceinline__ uint32_t smem_u32(const void* p) {
    uint32_t a;
    asm("{ .reg .u64 t; cvta.to.shared.u64 t, %1; cvt.u32.u64 %0, t; }" : "=r"(a) : "l"(p));
    return a;
}
__device__ __forceinline__ void cp16(uint32_t d, const void* s, bool pred) {
    int sz = pred ? 16 : 0;
    asm volatile("cp.async.cg.shared.global [%0], [%1], 16, %2;"
                 :: "r"(d), "l"(s), "r"(sz) : "memory");
}
__device__ __forceinline__ void cp_commit() {
    asm volatile("cp.async.commit_group;" ::: "memory");
}
#define CP_WAIT(n) asm volatile("cp.async.wait_group %0;" :: "n"(n) : "memory")

// ---------------- gap ----------------
__global__ void k_gap(const float* __restrict__ x) {
    int bc = blockIdx.x;
    int tid = threadIdx.x;
    __shared__ float red[256];
    const float4* p = (const float4*)(x + (size_t)bc * NL);
    float s = 0.f;
    for (int t = tid; t < NL/4; t += 256) { float4 v = p[t]; s += (v.x + v.y) + (v.z + v.w); }
    red[tid] = s; __syncthreads();
    for (int k = 128; k > 0; k >>= 1) { if (tid < k) red[tid] += red[tid+k]; __syncthreads(); }
    if (tid == 0) g_gap[bc >> 7][bc & 127] = red[0] * (1.0f / NL);
}

// ---------------- fold weights into g_Bt (original K order) ----------------
__global__ void k_prepw(const float* __restrict__ wp,  const float* __restrict__ wout,
                        const float* __restrict__ wdw, const float* __restrict__ win,
                        const float* __restrict__ w2,  const float* __restrict__ b2,
                        const float* __restrict__ dwp) {
    int o = blockIdx.x, c = threadIdx.x;
    __shared__ float wps[NC], q[NC], red[NC];
    wps[c] = wp[o*NC + c];
    __syncthreads();
    float a = 0.f;
    #pragma unroll 8
    for (int t = 0; t < NC; t++) a = fmaf(wps[t], wout[t*NC + c], a);
    q[c] = a;
    __syncthreads();
    float a1 = 0.f, a2 = 0.f;
    #pragma unroll 8
    for (int s = 0; s < NC; s++) {
        float qs = q[s];
        float w1 = wdw[s*3 + 1], w02 = wdw[s*3 + 0] + wdw[s*3 + 2];
        float wi = win[s*NC + c];
        a1 = fmaf(qs * w1,  wi, a1);
        a2 = fmaf(qs * w02, wi, a2);
    }
    a1 += wps[c];
    g_Bt[c*NC + o]          = to_tf32(a1);              // k 0..127:   B1 = Wp(M1+I)
    g_Bt[(NC + c)*NC + o]   = to_tf32(0.25f * a2);      // k 128..255: B2
    g_Bt[(2*NC + c)*NC + o] = to_tf32(dwp[0] * wps[c]); // k 256..383: B3
    if (c < NMID) {
        float s4 = 0.f;
        #pragma unroll 8
        for (int t = 0; t < NC; t++) s4 = fmaf(wps[t], w2[t*NMID + c], s4);
        g_Bt[(3*NC + c)*NC + o] = to_tf32(s4);          // k 384..415: Wp*W2
    }
    red[c] = wps[c] * b2[c];
    __syncthreads();
    for (int s = 64; s > 0; s >>= 1) { if (c < s) red[c] += red[c+s]; __syncthreads(); }
    if (c == 0) g_b2p[o] = red[0];
}

// ---------------- per-batch vectors ----------------
__global__ void k_prep3(const float* __restrict__ wci, const float* __restrict__ wdwch,
                        const float* __restrict__ wco, const float* __restrict__ w1) {
    int b = blockIdx.x, c = threadIdx.x;
    __shared__ float red[NC], gs[NC], g2s[NC];
    float g = g_gap[b][c];
    red[c] = g * g; __syncthreads();
    for (int s = 64; s > 0; s >>= 1) { if (c < s) red[c] += red[c+s]; __syncthreads(); }
    float nrm = fmaxf(sqrtf(red[0]), 1e-12f);
    gs[c] = g / nrm;
    __syncthreads();
    float a = 0.f;
    #pragma unroll 8
    for (int j = 0; j < NC; j++) a = fmaf(gs[j], wco[j*NC + c], a);
    g2s[c] = a;
    __syncthreads();
    float s0 = 0.f, s1 = 0.f, s2 = 0.f;
    #pragma unroll 8
    for (int t = 0; t < NC; t++) {
        float wv = wci[t*NC + c] * g2s[t];
        s0 = fmaf(wv, wdwch[t*3 + 0], s0);
        s1 = fmaf(wv, wdwch[t*3 + 1], s1);
        s2 = fmaf(wv, wdwch[t*3 + 2], s2);
    }
    g_ck[b][0][c] = s0; g_ck[b][1][c] = s1; g_ck[b][2][c] = s2;
    if (c < NMID) {
        float s = 0.f;
        #pragma unroll 8
        for (int t = 0; t < NC; t++) s = fmaf(w1[c*NC + t], gs[t], s);
        g_u[b][c] = s;
    }
}

// ---------------- stencil build: nsum + diff rows, no smem, float4 ----------------
// grid = NB*NC blocks (one channel plane each), 256 threads x 16 float4 iters
__global__ __launch_bounds__(256) void k_build(const float* __restrict__ x) {
    const int bx = blockIdx.x;
    const int b = bx >> 7, c = bx & 127;
    const float* xp = x + (size_t)(b*NC + c) * NL;
    float* nrow = g_Fg + (size_t)b*NFROWS*NL + (size_t)c*NL;
    float* drow = nrow + (size_t)NC*NL;
    const int tid = threadIdx.x;
    #pragma unroll 2
    for (int r = 0; r < 16; r++) {
        int p4 = tid + (r << 8);           // float4 index in plane
        int pos = p4 << 2;
        int i = pos >> 7, j0 = pos & 127;
        float4 c4 = ((const float4*)xp)[p4];
        float lprev = (pos > 0) ? xp[pos-1] : 0.f;
        float rnext = (pos < NL-4) ? xp[pos+4] : 0.f;
        float u0,u1,u2,u3, d0,d1,d2,d3;
        float4 up4, dn4;
        if (i > 0) {
            up4 = ((const float4*)xp)[p4-32];
            u0 = up4.x; u1 = up4.y; u2 = up4.z; u3 = up4.w;
        } else {
            // col-scan wrap: u_k = x[127, j0+k-1] (0 at j==0)
            u0 = (j0 > 0) ? xp[127*NW + j0-1] : 0.f;
            u1 = xp[127*NW + j0];
            u2 = xp[127*NW + j0+1];
            u3 = xp[127*NW + j0+2];
        }
        if (i < 127) {
            dn4 = ((const float4*)xp)[p4+32];
            d0 = dn4.x; d1 = dn4.y; d2 = dn4.z; d3 = dn4.w;
        } else {
            // col-scan wrap: d_k = x[0, j0+k+1] (0 at j==127)
            d0 = xp[j0+1]; d1 = xp[j0+2]; d2 = xp[j0+3];
            d3 = (j0+3 < 127) ? xp[j0+4] : 0.f;
        }
        // flat-order l/r
        float l0 = lprev, l1 = c4.x, l2 = c4.y, l3 = c4.z;
        float r0 = c4.y, r1 = c4.z, r2 = c4.w, r3 = rnext;
        float4 ns = make_float4(to_tf32((l0+r0)+(u0+d0)), to_tf32((l1+r1)+(u1+d1)),
                                to_tf32((l2+r2)+(u2+d2)), to_tf32((l3+r3)+(u3+d3)));
        ((float4*)nrow)[p4] = ns;
        // reflect neighbors
        float lr0 = (j0 == 0) ? c4.y : lprev;
        float rr3 = (j0 == 124) ? c4.z : rnext;
        float ur0, ur1, ur2, ur3, dr0, dr1, dr2, dr3;
        if (i > 0) { ur0=u0; ur1=u1; ur2=u2; ur3=u3; }
        else       { ur0=d0; ur1=d1; ur2=d2; ur3=d3; }   // i==0: reflect = row+1 (dn4 valid)
        if (i < 127) { dr0=d0; dr1=d1; dr2=d2; dr3=d3; }
        else         { dr0=u0; dr1=u1; dr2=u2; dr3=u3; } // i==127: reflect = row-1 (up4 valid)
        float df0 = 0.25f*((fabsf(c4.x-lr0)+fabsf(c4.x-c4.y))+(fabsf(c4.x-ur0)+fabsf(c4.x-dr0)));
        float df1 = 0.25f*((fabsf(c4.y-c4.x)+fabsf(c4.y-c4.z))+(fabsf(c4.y-ur1)+fabsf(c4.y-dr1)));
        float df2 = 0.25f*((fabsf(c4.z-c4.y)+fabsf(c4.z-c4.w))+(fabsf(c4.z-ur2)+fabsf(c4.z-dr2)));
        float df3 = 0.25f*((fabsf(c4.w-c4.z)+fabsf(c4.w-rr3))+(fabsf(c4.w-ur3)+fabsf(c4.w-dr3)));
        ((float4*)drow)[p4] = make_float4(to_tf32(df0), to_tf32(df1), to_tf32(df2), to_tf32(df3));
    }
}

// ---------------- v reduction + silu rows (transposed, barrier-free loop) ----------------
// grid = NB*64, 288 threads; threads 0..257 compute s-vectors over a 258-pos halo
__global__ __launch_bounds__(288) void k_vred(const float* __restrict__ x,
                                              const float* __restrict__ b1) {
    __shared__ float s0s[258], s1s[258], s2s[258];
    __shared__ float cks[3*NC], us[NMID], b1s[NMID];
    const int tid = threadIdx.x;
    const int b = blockIdx.x >> 6;
    const int tb = (blockIdx.x & 63) << 8;
    const float* xb = x + (size_t)b * NC * NL;

    for (int q = tid; q < 3*NC; q += 288) cks[q] = (&g_ck[b][0][0])[q];
    if (tid < NMID) { us[tid] = g_u[b][tid]; b1s[tid] = b1[tid]; }
    __syncthreads();

    if (tid < 258) {
        int gpos = tb - 1 + tid;
        float a0 = 0.f, a1 = 0.f, a2 = 0.f;
        if (gpos >= 0 && gpos < NL) {
            const float* px = xb + gpos;
            #pragma unroll 4
            for (int c = 0; c < NC; c++) {
                float xv = px[(size_t)c * NL];
                a0 = fmaf(cks[c], xv, a0);
                a1 = fmaf(cks[NC + c], xv, a1);
                a2 = fmaf(cks[2*NC + c], xv, a2);
            }
        }
        s0s[tid] = a0; s1s[tid] = a1; s2s[tid] = a2;
    }
    __syncthreads();
    if (tid < 256) {
        float v = s0s[tid] + s1s[tid+1] + s2s[tid+2];
        float* dst = g_Fg + (size_t)b*NFROWS*NL + (size_t)(2*NC)*NL + tb + tid;
        #pragma unroll 4
        for (int m = 0; m < NMID; m++) {
            float z = fmaf(us[m], v, b1s[m]);
            dst[(size_t)m * NL] = to_tf32(z / (1.f + __expf(-z)));
        }
    }
}

// ---------------- streaming GEMM, 3-stage ring, one sync per panel ----------------
#define GSMEM (3*8192*4)

__global__ __launch_bounds__(256, 2) void k_gemm(const float* __restrict__ x) {
    extern __shared__ __align__(16) float sm[];
    const int tid = threadIdx.x;
    const int b = blockIdx.x >> 7;
    const int posb = (blockIdx.x & 127) << 7;
    const float* xb  = x + (size_t)b * NC * NL + posb;
    const float* fgb = g_Fg + (size_t)b * NFROWS * NL + posb;

    auto issueP = [&](int p, int st) {
        int k0 = p * 32;
        const float* bsrc = (k0 < NC) ? (xb + (size_t)k0 * NL) : (fgb + (size_t)(k0 - NC) * NL);
        const float* asrc = g_Bt + k0 * NC;
        uint32_t ab = smem_u32(sm + st * 8192);
        uint32_t bb = ab + 16384;
        #pragma unroll
        for (int r = 0; r < 4; r++) {
            int f = tid + (r << 8);
            int kr = f >> 5, j4 = f & 31;
            int sw = (kr*32 + (j4 ^ ((kr & 3) << 1))) * 16;
            cp16(ab + sw, asrc + kr*NC + (j4 << 2), true);
            cp16(bb + sw, bsrc + (size_t)kr*NL + (j4 << 2), true);
        }
        cp_commit();
    };
    issueP(0, 0); issueP(1, 1);

    const int lane = tid & 31, g = lane >> 2, tg = lane & 3;
    const int w = tid >> 5, mbase = (w >> 2) * 64, nbase = (w & 3) * 32;
    const int swa = tg << 3;
    float dacc[4][4][4];
    #pragma unroll
    for (int mt = 0; mt < 4; mt++)
        #pragma unroll
        for (int nt = 0; nt < 4; nt++)
            #pragma unroll
            for (int qq = 0; qq < 4; qq++) dacc[mt][nt][qq] = 0.f;

    auto mmaPanel = [&](const uint32_t* As, bool cvt) {
        const uint32_t* Fu = As + 4096;
        #pragma unroll
        for (int ks = 0; ks < 4; ks++) {
            const int kr = ks * 8;
            uint32_t af[4][4], bf[4][2];
            #pragma unroll
            for (int nt = 0; nt < 4; nt++) {
                int n = nbase + nt*8 + g;
                uint32_t v0 = Fu[(kr + tg)*128 + (n ^ swa)];
                uint32_t v1 = Fu[(kr + tg + 4)*128 + (n ^ swa)];
                bf[nt][0] = cvt ? cvt_rna_u(v0) : v0;
                bf[nt][1] = cvt ? cvt_rna_u(v1) : v1;
            }
            #pragma unroll
            for (int mt = 0; mt < 4; mt++) {
                int o = mbase + mt*16 + g;
                af[mt][0] = As[(kr + tg)*128 + (o ^ swa)];
                af[mt][1] = As[(kr + tg)*128 + ((o+8) ^ swa)];
                af[mt][2] = As[(kr + tg + 4)*128 + (o ^ swa)];
                af[mt][3] = As[(kr + tg + 4)*128 + ((o+8) ^ swa)];
            }
            #pragma unroll
            for (int mt = 0; mt < 4; mt++)
                #pragma unroll
                for (int nt = 0; nt < 4; nt++)
                    mma_tf32(dacc[mt][nt], af[mt], bf[nt]);
        }
    };

    int st = 0;
    #pragma unroll 1
    for (int p = 0; p < NPAN; p++) {
        if (p < NPAN-1) { CP_WAIT(1); } else { CP_WAIT(0); }
        __syncthreads();                       // stage p ready; all warps done with p-1
        if (p + 2 < NPAN) issueP(p + 2, (p + 2) % 3);   // overwrites stage of p-1: safe
        mmaPanel((const uint32_t*)(sm + st * 8192), p < 4);
        st = (st == 2) ? 0 : st + 1;
    }
    __syncthreads();                            // all MMAs done -> reuse sm

    // ---- epilogue: bias, y2 store, BN partials ----
    float* sred = sm;
    #pragma unroll
    for (int mt = 0; mt < 4; mt++) {
        int o0 = mbase + mt*16 + g, o1 = o0 + 8;
        float bb0 = g_b2p[o0], bb1 = g_b2p[o1];
        float* row0 = &g_y2[(size_t)(b*NC + o0) * NL + posb];
        float* row1 = &g_y2[(size_t)(b*NC + o1) * NL + posb];
        float s0 = 0.f, q0 = 0.f, s1 = 0.f, q1 = 0.f;
        #pragma unroll
        for (int nt = 0; nt < 4; nt++) {
            float v0 = dacc[mt][nt][0] + bb0, v1 = dacc[mt][nt][1] + bb0;
            float v2 = dacc[mt][nt][2] + bb1, v3 = dacc[mt][nt][3] + bb1;
            int j = nbase + nt*8 + 2*tg;
            *(float2*)(row0 + j) = make_float2(v0, v1);
            *(float2*)(row1 + j) = make_float2(v2, v3);
            s0 += v0 + v1; q0 = fmaf(v0, v0, q0); q0 = fmaf(v1, v1, q0);
            s1 += v2 + v3; q1 = fmaf(v2, v2, q1); q1 = fmaf(v3, v3, q1);
        }
        s0 += __shfl_xor_sync(0xffffffff, s0, 1); s0 += __shfl_xor_sync(0xffffffff, s0, 2);
        q0 += __shfl_xor_sync(0xffffffff, q0, 1); q0 += __shfl_xor_sync(0xffffffff, q0, 2);
        s1 += __shfl_xor_sync(0xffffffff, s1, 1); s1 += __shfl_xor_sync(0xffffffff, s1, 2);
        q1 += __shfl_xor_sync(0xffffffff, q1, 1); q1 += __shfl_xor_sync(0xffffffff, q1, 2);
        if (tg == 0) {
            int nwq = w & 3;
            sred[o0*4 + nwq] = s0; sred[512 + o0*4 + nwq] = q0;
            sred[o1*4 + nwq] = s1; sred[512 + o1*4 + nwq] = q1;
        }
    }
    __syncthreads();
    if (tid < NC) {
        float s = 0.f, q = 0.f;
        #pragma unroll
        for (int t = 0; t < 4; t++) { s += sred[tid*4 + t]; q += sred[512 + tid*4 + t]; }
        g_psum[tid*NROWBLK + blockIdx.x] = s;
        g_psq [tid*NROWBLK + blockIdx.x] = q;
    }
}

// ---------------- BN stats ----------------
__global__ void k_bnstat(const float* __restrict__ gamma, const float* __restrict__ beta) {
    int c = blockIdx.x, tid = threadIdx.x;
    __shared__ float s1[256], s2[256];
    float a = 0.f, q = 0.f;
    for (int t = tid; t < NROWBLK; t += 256) { a += g_psum[c*NROWBLK + t]; q += g_psq[c*NROWBLK + t]; }
    s1[tid] = a; s2[tid] = q; __syncthreads();
    for (int s = 128; s > 0; s >>= 1) {
        if (tid < s) { s1[tid] += s1[tid+s]; s2[tid] += s2[tid+s]; }
        __syncthreads();
    }
    if (tid == 0) {
        const float invN = 1.0f / (float)(NB * NL);
        float mu  = s1[0] * invN;
        float var = s2[0] * invN - mu * mu;
        float rs  = rsqrtf(var + 1e-5f);
        float sc  = gamma[c] * rs;
        g_scale[c] = sc;
        g_shift[c] = beta[c] - mu * sc;
    }
}

// ---------------- normalize ----------------
__global__ void k_norm(float* __restrict__ out) {
    int idx = blockIdx.x * blockDim.x + threadIdx.x;
    float4 v = ((const float4*)g_y2)[idx];
    int c = (idx >> 12) & 127;
    float sc = g_scale[c], sh = g_shift[c];
    v.x = fmaf(v.x, sc, sh); v.y = fmaf(v.y, sc, sh);
    v.z = fmaf(v.z, sc, sh); v.w = fmaf(v.w, sc, sh);
    ((float4*)out)[idx] = v;
}

// ---------------- launcher ----------------
extern "C" void kernel_launch(void* const* d_in, const int* in_sizes, int n_in,
                              void* d_out, int out_size) {
    const float* x            = (const float*)d_in[0];
    const float* w_spatial_in = (const float*)d_in[1];
    const float* w_dw_spatial = (const float*)d_in[2];
    const float* w_spatial_out= (const float*)d_in[3];
    const float* w_ch_in      = (const float*)d_in[4];
    const float* w_ch_dw      = (const float*)d_in[5];
    const float* w_ch_out     = (const float*)d_in[6];
    const float* w_mlp1       = (const float*)d_in[7];
    const float* b_mlp1       = (const float*)d_in[8];
    const float* w_mlp2       = (const float*)d_in[9];
    const float* b_mlp2       = (const float*)d_in[10];
    const float* diff_weight  = (const float*)d_in[11];
    const float* bn_gamma     = (const float*)d_in[12];
    const float* bn_beta      = (const float*)d_in[13];
    const float* w_out_proj   = (const float*)d_in[14];
    float* out = (float*)d_out;

    cudaFuncSetAttribute(k_gemm, cudaFuncAttributeMaxDynamicSharedMemorySize, GSMEM);

    k_prepw<<<NC, NC>>>(w_out_proj, w_spatial_out, w_dw_spatial, w_spatial_in,
                        w_mlp2, b_mlp2, diff_weight);
    k_gap  <<<NB*NC, 256>>>(x);
    k_prep3<<<NB, NC>>>(w_ch_in, w_ch_dw, w_ch_out, w_mlp1);
    k_build<<<NB*NC, 256>>>(x);
    k_vred <<<NB*64, 288>>>(x, b_mlp1);
    k_gemm <<<NROWBLK, 256, GSMEM>>>(x);
    k_bnstat<<<NC, 256>>>(bn_gamma, bn_beta);
    k_norm <<<NTOT/4/256, 256>>>(out);
}